// round 8
// baseline (speedup 1.0000x reference)
#include <cuda_runtime.h>
#include <cuda_bf16.h>
#include <cstdint>
#include <math.h>

#define BB   8
#define CIN  512
#define CC   256
#define LL   2048

// ---------------------------------------------------------------------------
// Scratch for the gamma != 0 fallback path.
// ---------------------------------------------------------------------------
__device__ float g_V[BB * CC * LL];
__device__ float g_Q[BB * CC * LL];
__device__ float g_K[BB * CC * LL];
__device__ float g_O[BB * CC * LL];
__device__ float g_E[BB * LL * LL];
__device__ volatile unsigned g_bar;

// ---------------------------------------------------------------------------
// mma.sync m16n8k16 bf16 + ldmatrix (sm_75/80 baseline — not arch-gated)
// ---------------------------------------------------------------------------
__device__ __forceinline__ void mma16816(float& c0, float& c1, float& c2, float& c3,
                                         uint32_t a0, uint32_t a1, uint32_t a2, uint32_t a3,
                                         uint32_t b0, uint32_t b1)
{
    asm volatile(
        "mma.sync.aligned.m16n8k16.row.col.f32.bf16.bf16.f32 "
        "{%0,%1,%2,%3}, {%4,%5,%6,%7}, {%8,%9}, {%0,%1,%2,%3};"
        : "+f"(c0), "+f"(c1), "+f"(c2), "+f"(c3)
        : "r"(a0), "r"(a1), "r"(a2), "r"(a3), "r"(b0), "r"(b1));
}

#define LDSM_X4(R0,R1,R2,R3,ADDR) \
    asm volatile("ldmatrix.sync.aligned.m8n8.x4.shared.b16 {%0,%1,%2,%3}, [%4];" \
        : "=r"(R0), "=r"(R1), "=r"(R2), "=r"(R3) : "r"(ADDR))
#define LDSM_X4_T(R0,R1,R2,R3,ADDR) \
    asm volatile("ldmatrix.sync.aligned.m8n8.x4.trans.shared.b16 {%0,%1,%2,%3}, [%4];" \
        : "=r"(R0), "=r"(R1), "=r"(R2), "=r"(R3) : "r"(ADDR))

__device__ __forceinline__ uint32_t smem_u32(const void* p) {
    uint32_t a;
    asm("{ .reg .u64 t; cvta.to.shared.u64 t, %1; cvt.u32.u64 %0, t; }"
        : "=r"(a) : "l"(p));
    return a;
}
__device__ __forceinline__ uint32_t pack_bf16x2(float a, float b) {
    uint32_t r;
    asm("cvt.rn.bf16x2.f32 %0, %1, %2;" : "=r"(r) : "f"(b), "f"(a));
    return r;
}

// Split one float4 into bf16 hi/lo pairs and store 8 B to each smem address.
__device__ __forceinline__ void cvt_store(uint32_t hiaddr, uint32_t loaddr, float4 v) {
    uint32_t h01 = pack_bf16x2(v.x, v.y);
    uint32_t h23 = pack_bf16x2(v.z, v.w);
    float hx = __uint_as_float(h01 << 16);
    float hy = __uint_as_float(h01 & 0xffff0000u);
    float hz = __uint_as_float(h23 << 16);
    float hw = __uint_as_float(h23 & 0xffff0000u);
    uint32_t l01 = pack_bf16x2(v.x - hx, v.y - hy);
    uint32_t l23 = pack_bf16x2(v.z - hz, v.w - hw);
    asm volatile("st.shared.v2.u32 [%0], {%1,%2};" :: "r"(hiaddr), "r"(h01), "r"(h23) : "memory");
    asm volatile("st.shared.v2.u32 [%0], {%1,%2};" :: "r"(loaddr), "r"(l01), "r"(l23) : "memory");
}

// Smem (double-buffered, BK=16):
// A: [128 m][16 k] bf16, row 32 B pad 48 -> 6144 B/tile.  ldmatrix phase m*3 mod 8 distinct.
// B: [16 k][128 n] bf16, row 256 B pad 272 -> 4352 B/tile. ldmatrix.trans phase k*17 mod 8 distinct.
#define AROW   48
#define BROW   272
#define ABUF   6144
#define BBUF   4352
#define SM_AHI 0
#define SM_ALO 12288
#define SM_BHI 24576
#define SM_BLO 33280
#define SM_TOT 41984    // < 48 KB default: no cudaFuncSetAttribute needed

// ---------------------------------------------------------------------------
// V = Wv @ x_b + bv via mma.sync bf16, 3-term split (hi*hi + hi*lo + lo*hi).
// BM=128, BN=128, BK=16, 256 thr, software-pipelined double buffer.
// ---------------------------------------------------------------------------
extern "C" __global__ void __launch_bounds__(256, 2)
gemm_v_mma(const float* __restrict__ x,
           const float* __restrict__ Wv,
           const float* __restrict__ bv,
           const float* __restrict__ gamma,
           float* __restrict__ out)
{
    extern __shared__ char sm[];
    const uint32_t sb = smem_u32(sm);
    const int tid  = threadIdx.x;
    const int wid  = tid >> 5;
    const int lane = tid & 31;
    const int g    = lane >> 2;
    const int t    = lane & 3;
    const int wm   = wid >> 1;         // warp m 0..3 (32 rows)
    const int wn   = wid & 1;          // warp n 0..1 (64 cols)

    const int bn = blockIdx.x;         // 0..15
    const int bm = blockIdx.y;         // 0..1
    const int bb = blockIdx.z;         // 0..7

    if (bn == 0 && bm == 0 && bb == 0 && tid == 0) g_bar = 0;

    float c[2][8][4];
#pragma unroll
    for (int mt = 0; mt < 2; mt++)
#pragma unroll
        for (int nt = 0; nt < 8; nt++)
#pragma unroll
            for (int q = 0; q < 4; q++) c[mt][nt][q] = 0.0f;

    const float* Ag = Wv + (size_t)(bm * 128) * CIN;
    const float* Bg = x + (size_t)bb * CIN * LL + bn * 128;

    // loader coordinates (per thread, 2 iterations each for A and B)
    const int aRow = tid >> 2;                  // 0..63 (+64 on it=1)
    const int aP   = tid & 3;                   // k-group of 4
    const int bK   = tid >> 5;                  // 0..7 (+8 on it=1)
    const int bP   = tid & 31;                  // n-group of 4
    const uint32_t aOff = (uint32_t)(aRow * AROW + aP * 8);
    const uint32_t bOff = (uint32_t)(bK * BROW + bP * 8);

    // ldmatrix per-lane bases
    const int lane15  = lane & 15;
    const uint32_t aLaneOff = (uint32_t)((wm * 32 + lane15) * AROW + (lane >> 4) * 16);
    const int bKrow = ((lane >> 3) & 1) * 8 + (lane & 7);
    const uint32_t bLaneOff = (uint32_t)(bKrow * BROW + (wn * 64 + (lane >> 4) * 8) * 2);

    float4 pa[2], pb[2];

    // ---- prologue: load + convert chunk 0 into buffer 0 ----
#pragma unroll
    for (int it = 0; it < 2; it++) {
        pa[it] = *(const float4*)(Ag + (size_t)(aRow + it * 64) * CIN + aP * 4);
        pb[it] = *(const float4*)(Bg + (size_t)(bK + it * 8) * LL + bP * 4);
    }
#pragma unroll
    for (int it = 0; it < 2; it++) {
        uint32_t ao = aOff + (uint32_t)(it * 64 * AROW);
        uint32_t bo = bOff + (uint32_t)(it * 8 * BROW);
        cvt_store(sb + SM_AHI + ao, sb + SM_ALO + ao, pa[it]);
        cvt_store(sb + SM_BHI + bo, sb + SM_BLO + bo, pb[it]);
    }
    __syncthreads();

    for (int ch = 0; ch < 32; ch++) {
        const uint32_t abuf = (uint32_t)((ch & 1) * ABUF);
        const uint32_t bbuf = (uint32_t)((ch & 1) * BBUF);

        // ---- issue next chunk's global loads first (latency hidden by mma) ----
        if (ch < 31) {
            const int k0 = (ch + 1) * 16;
#pragma unroll
            for (int it = 0; it < 2; it++) {
                pa[it] = *(const float4*)(Ag + (size_t)(aRow + it * 64) * CIN + k0 + aP * 4);
                pb[it] = *(const float4*)(Bg + (size_t)(k0 + bK + it * 8) * LL + bP * 4);
            }
        }

        // ---- compute on current buffer: 3 terms x 16 mma ----
        {
            uint32_t Ah[2][4], Bh[4][4], Bl4[4];

#pragma unroll
            for (int mt = 0; mt < 2; mt++)
                LDSM_X4(Ah[mt][0], Ah[mt][1], Ah[mt][2], Ah[mt][3],
                        sb + SM_AHI + abuf + aLaneOff + (uint32_t)(mt * 16 * AROW));
#pragma unroll
            for (int n2 = 0; n2 < 4; n2++)
                LDSM_X4_T(Bh[n2][0], Bh[n2][1], Bh[n2][2], Bh[n2][3],
                          sb + SM_BHI + bbuf + bLaneOff + (uint32_t)(n2 * 32));
            // hi * hi
#pragma unroll
            for (int mt = 0; mt < 2; mt++)
#pragma unroll
                for (int n2 = 0; n2 < 4; n2++) {
                    mma16816(c[mt][2*n2][0], c[mt][2*n2][1], c[mt][2*n2][2], c[mt][2*n2][3],
                             Ah[mt][0], Ah[mt][1], Ah[mt][2], Ah[mt][3],
                             Bh[n2][0], Bh[n2][1]);
                    mma16816(c[mt][2*n2+1][0], c[mt][2*n2+1][1], c[mt][2*n2+1][2], c[mt][2*n2+1][3],
                             Ah[mt][0], Ah[mt][1], Ah[mt][2], Ah[mt][3],
                             Bh[n2][2], Bh[n2][3]);
                }
            // hi * lo (B lo loaded per panel, consumed immediately: low reg peak)
#pragma unroll
            for (int n2 = 0; n2 < 4; n2++) {
                LDSM_X4_T(Bl4[0], Bl4[1], Bl4[2], Bl4[3],
                          sb + SM_BLO + bbuf + bLaneOff + (uint32_t)(n2 * 32));
#pragma unroll
                for (int mt = 0; mt < 2; mt++) {
                    mma16816(c[mt][2*n2][0], c[mt][2*n2][1], c[mt][2*n2][2], c[mt][2*n2][3],
                             Ah[mt][0], Ah[mt][1], Ah[mt][2], Ah[mt][3],
                             Bl4[0], Bl4[1]);
                    mma16816(c[mt][2*n2+1][0], c[mt][2*n2+1][1], c[mt][2*n2+1][2], c[mt][2*n2+1][3],
                             Ah[mt][0], Ah[mt][1], Ah[mt][2], Ah[mt][3],
                             Bl4[2], Bl4[3]);
                }
            }
            // lo * hi (A lo overwrites Ah)
#pragma unroll
            for (int mt = 0; mt < 2; mt++)
                LDSM_X4(Ah[mt][0], Ah[mt][1], Ah[mt][2], Ah[mt][3],
                        sb + SM_ALO + abuf + aLaneOff + (uint32_t)(mt * 16 * AROW));
#pragma unroll
            for (int mt = 0; mt < 2; mt++)
#pragma unroll
                for (int n2 = 0; n2 < 4; n2++) {
                    mma16816(c[mt][2*n2][0], c[mt][2*n2][1], c[mt][2*n2][2], c[mt][2*n2][3],
                             Ah[mt][0], Ah[mt][1], Ah[mt][2], Ah[mt][3],
                             Bh[n2][0], Bh[n2][1]);
                    mma16816(c[mt][2*n2+1][0], c[mt][2*n2+1][1], c[mt][2*n2+1][2], c[mt][2*n2+1][3],
                             Ah[mt][0], Ah[mt][1], Ah[mt][2], Ah[mt][3],
                             Bh[n2][2], Bh[n2][3]);
                }
        }

        // ---- convert + store next chunk into the other buffer ----
        if (ch < 31) {
            const uint32_t abuf2 = (uint32_t)(((ch + 1) & 1) * ABUF);
            const uint32_t bbuf2 = (uint32_t)(((ch + 1) & 1) * BBUF);
#pragma unroll
            for (int it = 0; it < 2; it++) {
                uint32_t ao = aOff + (uint32_t)(it * 64 * AROW);
                uint32_t bo = bOff + (uint32_t)(it * 8 * BROW);
                cvt_store(sb + SM_AHI + abuf2 + ao, sb + SM_ALO + abuf2 + ao, pa[it]);
                cvt_store(sb + SM_BHI + bbuf2 + bo, sb + SM_BLO + bbuf2 + bo, pb[it]);
            }
        }
        __syncthreads();
    }

    // ---- epilogue ----
    const float gma = gamma[0];
    float* obase = out + (size_t)bb * (2 * CC) * LL;

#pragma unroll
    for (int mt = 0; mt < 2; mt++) {
        const int m0 = bm * 128 + wm * 32 + mt * 16 + g;
        const float bv0 = bv[m0];
        const float bv1 = bv[m0 + 8];
#pragma unroll
        for (int nt = 0; nt < 8; nt++) {
            const int l0 = bn * 128 + wn * 64 + nt * 8 + 2 * t;
            float2 r0 = make_float2(c[mt][nt][0] + bv0, c[mt][nt][1] + bv0);
            float2 r1 = make_float2(c[mt][nt][2] + bv1, c[mt][nt][3] + bv1);
            *(float2*)(obase + (size_t)(m0    ) * LL + l0) = r0;
            *(float2*)(obase + (size_t)(m0 + 8) * LL + l0) = r1;
            if (gma != 0.0f) {
                float* vs = g_V + (size_t)bb * CC * LL;
                *(float2*)(vs + (size_t)(m0    ) * LL + l0) = r0;
                *(float2*)(vs + (size_t)(m0 + 8) * LL + l0) = r1;
            } else {
                const float2 z = make_float2(0.f, 0.f);
                *(float2*)(obase + (size_t)(CC + m0    ) * LL + l0) = z;
                *(float2*)(obase + (size_t)(CC + m0 + 8) * LL + l0) = z;
            }
        }
    }
}

// ---------------------------------------------------------------------------
// Persistent guarded fallback (gamma != 0 only).
// ---------------------------------------------------------------------------
#define FB_GRID 64

__device__ void fb_bar(unsigned target) {
    __syncthreads();
    if (threadIdx.x == 0) {
        __threadfence();
        atomicAdd((unsigned*)&g_bar, 1u);
        while (g_bar < target) __nanosleep(200);
    }
    __syncthreads();
    __threadfence();
}

extern "C" __global__ void fallback_attn(
    const float* __restrict__ Wq, const float* __restrict__ bq,
    const float* __restrict__ Wk, const float* __restrict__ bk,
    const float* __restrict__ Wc, const float* __restrict__ bc,
    const float* __restrict__ gamma, float* __restrict__ out)
{
    const float g = gamma[0];
    if (g == 0.0f) return;

    const int nthr = FB_GRID * 256;
    const int gtid = blockIdx.x * 256 + threadIdx.x;

    {   // Q, K projections
        const size_t total = (size_t)BB * CC * LL;
        for (size_t w = gtid; w < total; w += nthr) {
            int l = (int)(w % LL);
            int o = (int)((w / LL) % CC);
            int b = (int)(w / ((size_t)CC * LL));
            float sq = bq[o], sk = bk[o];
            for (int cc = 0; cc < CC; cc++) {
                float vv = g_V[((size_t)b * CC + cc) * LL + l];
                sq = fmaf(Wq[o * CC + cc], vv, sq);
                sk = fmaf(Wk[o * CC + cc], vv, sk);
            }
            g_Q[w] = sq; g_K[w] = sk;
        }
    }
    fb_bar(1 * FB_GRID);

    {   // energy
        const size_t total = (size_t)BB * LL * LL;
        for (size_t w = gtid; w < total; w += nthr) {
            int j = (int)(w % LL);
            int i = (int)((w / LL) % LL);
            int b = (int)(w / ((size_t)LL * LL));
            float s = 0.0f;
            for (int cc = 0; cc < CC; cc++)
                s = fmaf(g_Q[((size_t)b * CC + cc) * LL + i],
                         g_K[((size_t)b * CC + cc) * LL + j], s);
            g_E[w] = s;
        }
    }
    fb_bar(2 * FB_GRID);

    {   // softmax rows (in place)
        __shared__ float red[256];
        const int tidl = threadIdx.x;
        for (int r = blockIdx.x; r < BB * LL; r += FB_GRID) {
            float* row = g_E + (size_t)r * LL;
            float mx = -INFINITY;
            for (int j = tidl; j < LL; j += 256) mx = fmaxf(mx, row[j]);
            red[tidl] = mx; __syncthreads();
            for (int s = 128; s > 0; s >>= 1) {
                if (tidl < s) red[tidl] = fmaxf(red[tidl], red[tidl + s]);
                __syncthreads();
            }
            mx = red[0]; __syncthreads();
            float sum = 0.0f;
            for (int j = tidl; j < LL; j += 256) {
                float e = expf(row[j] - mx);
                row[j] = e; sum += e;
            }
            red[tidl] = sum; __syncthreads();
            for (int s = 128; s > 0; s >>= 1) {
                if (tidl < s) red[tidl] += red[tidl + s];
                __syncthreads();
            }
            const float inv = 1.0f / red[0];
            __syncthreads();
            for (int j = tidl; j < LL; j += 256) row[j] *= inv;
            __syncthreads();
        }
    }
    fb_bar(3 * FB_GRID);

    {   // out_attn = V @ attn^T
        const size_t total = (size_t)BB * CC * LL;
        for (size_t w = gtid; w < total; w += nthr) {
            int i = (int)(w % LL);
            int cc = (int)((w / LL) % CC);
            int b = (int)(w / ((size_t)CC * LL));
            const float* vrow = g_V + ((size_t)b * CC + cc) * LL;
            const float* prow = g_E + ((size_t)b * LL + i) * LL;
            float s = 0.0f;
            for (int j = 0; j < LL; j++) s = fmaf(vrow[j], prow[j], s);
            g_O[((size_t)b * CC + cc) * LL + i] = s;
        }
    }
    fb_bar(4 * FB_GRID);

    {   // bottom half = gamma * (Wc @ O + bc)
        const size_t total = (size_t)BB * CC * LL;
        for (size_t w = gtid; w < total; w += nthr) {
            int l = (int)(w % LL);
            int o = (int)((w / LL) % CC);
            int b = (int)(w / ((size_t)CC * LL));
            float s = bc[o];
            for (int cc = 0; cc < CC; cc++)
                s = fmaf(Wc[o * CC + cc], g_O[((size_t)b * CC + cc) * LL + l], s);
            out[(size_t)b * (2 * CC) * LL + (size_t)(CC + o) * LL + l] = g * s;
        }
    }
}

// ---------------------------------------------------------------------------
extern "C" void kernel_launch(void* const* d_in, const int* in_sizes, int n_in,
                              void* d_out, int out_size)
{
    const float* x     = (const float*)d_in[0];
    const float* Wv    = (const float*)d_in[1];
    const float* bv    = (const float*)d_in[2];
    const float* Wq    = (const float*)d_in[3];
    const float* bq    = (const float*)d_in[4];
    const float* Wk    = (const float*)d_in[5];
    const float* bk    = (const float*)d_in[6];
    const float* Wc    = (const float*)d_in[7];
    const float* bc    = (const float*)d_in[8];
    const float* gamma = (const float*)d_in[9];
    float* out = (float*)d_out;

    dim3 grid(16, 2, 8);
    gemm_v_mma<<<grid, 256, SM_TOT>>>(x, Wv, bv, gamma, out);
    fallback_attn<<<FB_GRID, 256>>>(Wq, bq, Wk, bk, Wc, bc, gamma, out);
}

// round 9
// speedup vs baseline: 1.2422x; 1.2422x over previous
#include <cuda_runtime.h>
#include <cuda_fp16.h>
#include <cstdint>
#include <math.h>

#define BB   8
#define CIN  512
#define CC   256
#define LL   2048

// ---------------------------------------------------------------------------
// Scratch for the gamma != 0 fallback path.
// ---------------------------------------------------------------------------
__device__ float g_V[BB * CC * LL];
__device__ float g_Q[BB * CC * LL];
__device__ float g_K[BB * CC * LL];
__device__ float g_O[BB * CC * LL];
__device__ float g_E[BB * LL * LL];
__device__ volatile unsigned g_bar;

// ---------------------------------------------------------------------------
// mma.sync m16n8k16 fp16 + ldmatrix (sm_75/80 baseline — not arch-gated)
// ---------------------------------------------------------------------------
__device__ __forceinline__ void mma16816(float& c0, float& c1, float& c2, float& c3,
                                         uint32_t a0, uint32_t a1, uint32_t a2, uint32_t a3,
                                         uint32_t b0, uint32_t b1)
{
    asm volatile(
        "mma.sync.aligned.m16n8k16.row.col.f32.f16.f16.f32 "
        "{%0,%1,%2,%3}, {%4,%5,%6,%7}, {%8,%9}, {%0,%1,%2,%3};"
        : "+f"(c0), "+f"(c1), "+f"(c2), "+f"(c3)
        : "r"(a0), "r"(a1), "r"(a2), "r"(a3), "r"(b0), "r"(b1));
}

#define LDSM_X4(R0,R1,R2,R3,ADDR) \
    asm volatile("ldmatrix.sync.aligned.m8n8.x4.shared.b16 {%0,%1,%2,%3}, [%4];" \
        : "=r"(R0), "=r"(R1), "=r"(R2), "=r"(R3) : "r"(ADDR))
#define LDSM_X4_T(R0,R1,R2,R3,ADDR) \
    asm volatile("ldmatrix.sync.aligned.m8n8.x4.trans.shared.b16 {%0,%1,%2,%3}, [%4];" \
        : "=r"(R0), "=r"(R1), "=r"(R2), "=r"(R3) : "r"(ADDR))

__device__ __forceinline__ uint32_t smem_u32(const void* p) {
    uint32_t a;
    asm("{ .reg .u64 t; cvta.to.shared.u64 t, %1; cvt.u32.u64 %0, t; }"
        : "=r"(a) : "l"(p));
    return a;
}

// Pack two fp16 (lo = a, hi = b) from floats.
__device__ __forceinline__ uint32_t pack_f16x2(float a, float b) {
    __half2 h = __halves2half2(__float2half_rn(a), __float2half_rn(b));
    return *reinterpret_cast<uint32_t*>(&h);
}

// A (weights): fp16 hi only — one 8 B store per float4.
__device__ __forceinline__ void cvt_store_hi(uint32_t addr, float4 v) {
    uint32_t h01 = pack_f16x2(v.x, v.y);
    uint32_t h23 = pack_f16x2(v.z, v.w);
    asm volatile("st.shared.v2.u32 [%0], {%1,%2};" :: "r"(addr), "r"(h01), "r"(h23) : "memory");
}

// B (x): fp16 hi + lo (lo = exact residual, error ~2^-24).
__device__ __forceinline__ void cvt_store_hilo(uint32_t hiaddr, uint32_t loaddr, float4 v) {
    __half hx = __float2half_rn(v.x), hy = __float2half_rn(v.y);
    __half hz = __float2half_rn(v.z), hw = __float2half_rn(v.w);
    uint32_t h01, h23;
    {   __half2 p = __halves2half2(hx, hy); h01 = *reinterpret_cast<uint32_t*>(&p); }
    {   __half2 p = __halves2half2(hz, hw); h23 = *reinterpret_cast<uint32_t*>(&p); }
    uint32_t l01 = pack_f16x2(v.x - __half2float(hx), v.y - __half2float(hy));
    uint32_t l23 = pack_f16x2(v.z - __half2float(hz), v.w - __half2float(hw));
    asm volatile("st.shared.v2.u32 [%0], {%1,%2};" :: "r"(hiaddr), "r"(h01), "r"(h23) : "memory");
    asm volatile("st.shared.v2.u32 [%0], {%1,%2};" :: "r"(loaddr), "r"(l01), "r"(l23) : "memory");
}

// Smem (double-buffered, BK=16):
// A: [128 m][16 k] fp16, row 32 B pad 48 -> 6144 B/tile.  ldmatrix phase m*3 mod 8 distinct.
// B: [16 k][128 n] fp16, row 256 B pad 272 -> 4352 B/tile. ldmatrix.trans phase k*17 mod 8 distinct.
#define AROW   48
#define BROW   272
#define ABUF   6144
#define BBUF   4352
#define SM_A   0                 // 2 x 6144
#define SM_BHI 12288             // 2 x 4352
#define SM_BLO 20992             // 2 x 4352
#define SM_TOT 29696             // < 48 KB default

// ---------------------------------------------------------------------------
// V = Wv @ x_b + bv via mma.sync fp16, 2-term split (Wh*xh + Wh*xl).
// BM=128, BN=128, BK=16, 256 thr, software-pipelined double buffer.
// ---------------------------------------------------------------------------
extern "C" __global__ void __launch_bounds__(256, 2)
gemm_v_mma(const float* __restrict__ x,
           const float* __restrict__ Wv,
           const float* __restrict__ bv,
           const float* __restrict__ gamma,
           float* __restrict__ out)
{
    extern __shared__ char sm[];
    const uint32_t sb = smem_u32(sm);
    const int tid  = threadIdx.x;
    const int wid  = tid >> 5;
    const int lane = tid & 31;
    const int g    = lane >> 2;
    const int t    = lane & 3;
    const int wm   = wid >> 1;         // warp m 0..3 (32 rows)
    const int wn   = wid & 1;          // warp n 0..1 (64 cols)

    const int bn = blockIdx.x;         // 0..15
    const int bm = blockIdx.y;         // 0..1
    const int bb = blockIdx.z;         // 0..7

    if (bn == 0 && bm == 0 && bb == 0 && tid == 0) g_bar = 0;

    float c[2][8][4];
#pragma unroll
    for (int mt = 0; mt < 2; mt++)
#pragma unroll
        for (int nt = 0; nt < 8; nt++)
#pragma unroll
            for (int q = 0; q < 4; q++) c[mt][nt][q] = 0.0f;

    const float* Ag = Wv + (size_t)(bm * 128) * CIN;
    const float* Bg = x + (size_t)bb * CIN * LL + bn * 128;

    // loader coordinates
    const int aRow = tid >> 2;                  // 0..63 (+64 on it=1)
    const int aP   = tid & 3;
    const int bK   = tid >> 5;                  // 0..7 (+8 on it=1)
    const int bP   = tid & 31;
    const uint32_t aOff = (uint32_t)(aRow * AROW + aP * 8);
    const uint32_t bOff = (uint32_t)(bK * BROW + bP * 8);

    // ldmatrix per-lane bases
    const int lane15  = lane & 15;
    const uint32_t aLaneOff = (uint32_t)((wm * 32 + lane15) * AROW + (lane >> 4) * 16);
    const int bKrow = ((lane >> 3) & 1) * 8 + (lane & 7);
    const uint32_t bLaneOff = (uint32_t)(bKrow * BROW + (wn * 64 + (lane >> 4) * 8) * 2);

    float4 pa[2], pb[2];

    // ---- prologue: load + convert chunk 0 into buffer 0 ----
#pragma unroll
    for (int it = 0; it < 2; it++) {
        pa[it] = *(const float4*)(Ag + (size_t)(aRow + it * 64) * CIN + aP * 4);
        pb[it] = *(const float4*)(Bg + (size_t)(bK + it * 8) * LL + bP * 4);
    }
#pragma unroll
    for (int it = 0; it < 2; it++) {
        uint32_t ao = aOff + (uint32_t)(it * 64 * AROW);
        uint32_t bo = bOff + (uint32_t)(it * 8 * BROW);
        cvt_store_hi(sb + SM_A + ao, pa[it]);
        cvt_store_hilo(sb + SM_BHI + bo, sb + SM_BLO + bo, pb[it]);
    }
    __syncthreads();

    for (int ch = 0; ch < 32; ch++) {
        const uint32_t abuf = (uint32_t)((ch & 1) * ABUF);
        const uint32_t bbuf = (uint32_t)((ch & 1) * BBUF);

        // next chunk's global loads first (latency hidden under mma)
        if (ch < 31) {
            const int k0 = (ch + 1) * 16;
#pragma unroll
            for (int it = 0; it < 2; it++) {
                pa[it] = *(const float4*)(Ag + (size_t)(aRow + it * 64) * CIN + k0 + aP * 4);
                pb[it] = *(const float4*)(Bg + (size_t)(k0 + bK + it * 8) * LL + bP * 4);
            }
        }

        // ---- compute: 2 terms x 16 mma ----
        {
            uint32_t Ah[2][4], Bf[4][4];

#pragma unroll
            for (int mt = 0; mt < 2; mt++)
                LDSM_X4(Ah[mt][0], Ah[mt][1], Ah[mt][2], Ah[mt][3],
                        sb + SM_A + abuf + aLaneOff + (uint32_t)(mt * 16 * AROW));
#pragma unroll
            for (int n2 = 0; n2 < 4; n2++)
                LDSM_X4_T(Bf[n2][0], Bf[n2][1], Bf[n2][2], Bf[n2][3],
                          sb + SM_BHI + bbuf + bLaneOff + (uint32_t)(n2 * 32));
            // Wh * xh
#pragma unroll
            for (int mt = 0; mt < 2; mt++)
#pragma unroll
                for (int n2 = 0; n2 < 4; n2++) {
                    mma16816(c[mt][2*n2][0], c[mt][2*n2][1], c[mt][2*n2][2], c[mt][2*n2][3],
                             Ah[mt][0], Ah[mt][1], Ah[mt][2], Ah[mt][3],
                             Bf[n2][0], Bf[n2][1]);
                    mma16816(c[mt][2*n2+1][0], c[mt][2*n2+1][1], c[mt][2*n2+1][2], c[mt][2*n2+1][3],
                             Ah[mt][0], Ah[mt][1], Ah[mt][2], Ah[mt][3],
                             Bf[n2][2], Bf[n2][3]);
                }
            // Wh * xl (B lo loaded per panel, consumed immediately)
#pragma unroll
            for (int n2 = 0; n2 < 4; n2++) {
                uint32_t Bl4[4];
                LDSM_X4_T(Bl4[0], Bl4[1], Bl4[2], Bl4[3],
                          sb + SM_BLO + bbuf + bLaneOff + (uint32_t)(n2 * 32));
#pragma unroll
                for (int mt = 0; mt < 2; mt++) {
                    mma16816(c[mt][2*n2][0], c[mt][2*n2][1], c[mt][2*n2][2], c[mt][2*n2][3],
                             Ah[mt][0], Ah[mt][1], Ah[mt][2], Ah[mt][3],
                             Bl4[0], Bl4[1]);
                    mma16816(c[mt][2*n2+1][0], c[mt][2*n2+1][1], c[mt][2*n2+1][2], c[mt][2*n2+1][3],
                             Ah[mt][0], Ah[mt][1], Ah[mt][2], Ah[mt][3],
                             Bl4[2], Bl4[3]);
                }
            }
        }

        // ---- convert + store next chunk into the other buffer ----
        if (ch < 31) {
            const uint32_t abuf2 = (uint32_t)(((ch + 1) & 1) * ABUF);
            const uint32_t bbuf2 = (uint32_t)(((ch + 1) & 1) * BBUF);
#pragma unroll
            for (int it = 0; it < 2; it++) {
                uint32_t ao = aOff + (uint32_t)(it * 64 * AROW);
                uint32_t bo = bOff + (uint32_t)(it * 8 * BROW);
                cvt_store_hi(sb + SM_A + abuf2 + ao, pa[it]);
                cvt_store_hilo(sb + SM_BHI + bbuf2 + bo, sb + SM_BLO + bbuf2 + bo, pb[it]);
            }
        }
        __syncthreads();
    }

    // ---- epilogue ----
    const float gma = gamma[0];
    float* obase = out + (size_t)bb * (2 * CC) * LL;

#pragma unroll
    for (int mt = 0; mt < 2; mt++) {
        const int m0 = bm * 128 + wm * 32 + mt * 16 + g;
        const float bv0 = bv[m0];
        const float bv1 = bv[m0 + 8];
#pragma unroll
        for (int nt = 0; nt < 8; nt++) {
            const int l0 = bn * 128 + wn * 64 + nt * 8 + 2 * t;
            float2 r0 = make_float2(c[mt][nt][0] + bv0, c[mt][nt][1] + bv0);
            float2 r1 = make_float2(c[mt][nt][2] + bv1, c[mt][nt][3] + bv1);
            *(float2*)(obase + (size_t)(m0    ) * LL + l0) = r0;
            *(float2*)(obase + (size_t)(m0 + 8) * LL + l0) = r1;
            if (gma != 0.0f) {
                float* vs = g_V + (size_t)bb * CC * LL;
                *(float2*)(vs + (size_t)(m0    ) * LL + l0) = r0;
                *(float2*)(vs + (size_t)(m0 + 8) * LL + l0) = r1;
            } else {
                const float2 z = make_float2(0.f, 0.f);
                *(float2*)(obase + (size_t)(CC + m0    ) * LL + l0) = z;
                *(float2*)(obase + (size_t)(CC + m0 + 8) * LL + l0) = z;
            }
        }
    }
}

// ---------------------------------------------------------------------------
// Persistent guarded fallback (gamma != 0 only).
// ---------------------------------------------------------------------------
#define FB_GRID 64

__device__ void fb_bar(unsigned target) {
    __syncthreads();
    if (threadIdx.x == 0) {
        __threadfence();
        atomicAdd((unsigned*)&g_bar, 1u);
        while (g_bar < target) __nanosleep(200);
    }
    __syncthreads();
    __threadfence();
}

extern "C" __global__ void fallback_attn(
    const float* __restrict__ Wq, const float* __restrict__ bq,
    const float* __restrict__ Wk, const float* __restrict__ bk,
    const float* __restrict__ Wc, const float* __restrict__ bc,
    const float* __restrict__ gamma, float* __restrict__ out)
{
    const float g = gamma[0];
    if (g == 0.0f) return;

    const int nthr = FB_GRID * 256;
    const int gtid = blockIdx.x * 256 + threadIdx.x;

    {   // Q, K projections
        const size_t total = (size_t)BB * CC * LL;
        for (size_t w = gtid; w < total; w += nthr) {
            int l = (int)(w % LL);
            int o = (int)((w / LL) % CC);
            int b = (int)(w / ((size_t)CC * LL));
            float sq = bq[o], sk = bk[o];
            for (int cc = 0; cc < CC; cc++) {
                float vv = g_V[((size_t)b * CC + cc) * LL + l];
                sq = fmaf(Wq[o * CC + cc], vv, sq);
                sk = fmaf(Wk[o * CC + cc], vv, sk);
            }
            g_Q[w] = sq; g_K[w] = sk;
        }
    }
    fb_bar(1 * FB_GRID);

    {   // energy
        const size_t total = (size_t)BB * LL * LL;
        for (size_t w = gtid; w < total; w += nthr) {
            int j = (int)(w % LL);
            int i = (int)((w / LL) % LL);
            int b = (int)(w / ((size_t)LL * LL));
            float s = 0.0f;
            for (int cc = 0; cc < CC; cc++)
                s = fmaf(g_Q[((size_t)b * CC + cc) * LL + i],
                         g_K[((size_t)b * CC + cc) * LL + j], s);
            g_E[w] = s;
        }
    }
    fb_bar(2 * FB_GRID);

    {   // softmax rows (in place)
        __shared__ float red[256];
        const int tidl = threadIdx.x;
        for (int r = blockIdx.x; r < BB * LL; r += FB_GRID) {
            float* row = g_E + (size_t)r * LL;
            float mx = -INFINITY;
            for (int j = tidl; j < LL; j += 256) mx = fmaxf(mx, row[j]);
            red[tidl] = mx; __syncthreads();
            for (int s = 128; s > 0; s >>= 1) {
                if (tidl < s) red[tidl] = fmaxf(red[tidl], red[tidl + s]);
                __syncthreads();
            }
            mx = red[0]; __syncthreads();
            float sum = 0.0f;
            for (int j = tidl; j < LL; j += 256) {
                float e = expf(row[j] - mx);
                row[j] = e; sum += e;
            }
            red[tidl] = sum; __syncthreads();
            for (int s = 128; s > 0; s >>= 1) {
                if (tidl < s) red[tidl] += red[tidl + s];
                __syncthreads();
            }
            const float inv = 1.0f / red[0];
            __syncthreads();
            for (int j = tidl; j < LL; j += 256) row[j] *= inv;
            __syncthreads();
        }
    }
    fb_bar(3 * FB_GRID);

    {   // out_attn = V @ attn^T
        const size_t total = (size_t)BB * CC * LL;
        for (size_t w = gtid; w < total; w += nthr) {
            int i = (int)(w % LL);
            int cc = (int)((w / LL) % CC);
            int b = (int)(w / ((size_t)CC * LL));
            const float* vrow = g_V + ((size_t)b * CC + cc) * LL;
            const float* prow = g_E + ((size_t)b * LL + i) * LL;
            float s = 0.0f;
            for (int j = 0; j < LL; j++) s = fmaf(vrow[j], prow[j], s);
            g_O[((size_t)b * CC + cc) * LL + i] = s;
        }
    }
    fb_bar(4 * FB_GRID);

    {   // bottom half = gamma * (Wc @ O + bc)
        const size_t total = (size_t)BB * CC * LL;
        for (size_t w = gtid; w < total; w += nthr) {
            int l = (int)(w % LL);
            int o = (int)((w / LL) % CC);
            int b = (int)(w / ((size_t)CC * LL));
            float s = bc[o];
            for (int cc = 0; cc < CC; cc++)
                s = fmaf(Wc[o * CC + cc], g_O[((size_t)b * CC + cc) * LL + l], s);
            out[(size_t)b * (2 * CC) * LL + (size_t)(CC + o) * LL + l] = g * s;
        }
    }
}

// ---------------------------------------------------------------------------
extern "C" void kernel_launch(void* const* d_in, const int* in_sizes, int n_in,
                              void* d_out, int out_size)
{
    const float* x     = (const float*)d_in[0];
    const float* Wv    = (const float*)d_in[1];
    const float* bv    = (const float*)d_in[2];
    const float* Wq    = (const float*)d_in[3];
    const float* bq    = (const float*)d_in[4];
    const float* Wk    = (const float*)d_in[5];
    const float* bk    = (const float*)d_in[6];
    const float* Wc    = (const float*)d_in[7];
    const float* bc    = (const float*)d_in[8];
    const float* gamma = (const float*)d_in[9];
    float* out = (float*)d_out;

    dim3 grid(16, 2, 8);
    gemm_v_mma<<<grid, 256, SM_TOT>>>(x, Wv, bv, gamma, out);
    fallback_attn<<<FB_GRID, 256>>>(Wq, bq, Wk, bk, Wc, bc, gamma, out);
}

// round 10
// speedup vs baseline: 1.7111x; 1.3774x over previous
#include <cuda_runtime.h>
#include <cuda_fp16.h>
#include <cstdint>
#include <math.h>

#define BB   8
#define CIN  512
#define CC   256
#define LL   2048

// ---------------------------------------------------------------------------
// Scratch for the gamma != 0 fallback path.
// ---------------------------------------------------------------------------
__device__ float g_V[BB * CC * LL];
__device__ float g_Q[BB * CC * LL];
__device__ float g_K[BB * CC * LL];
__device__ float g_O[BB * CC * LL];
__device__ float g_E[BB * LL * LL];
__device__ volatile unsigned g_bar;

// ---------------------------------------------------------------------------
// mma.sync m16n8k16 fp16 + ldmatrix (sm_75/80 baseline — not arch-gated)
// ---------------------------------------------------------------------------
__device__ __forceinline__ void mma16816(float& c0, float& c1, float& c2, float& c3,
                                         uint32_t a0, uint32_t a1, uint32_t a2, uint32_t a3,
                                         uint32_t b0, uint32_t b1)
{
    asm volatile(
        "mma.sync.aligned.m16n8k16.row.col.f32.f16.f16.f32 "
        "{%0,%1,%2,%3}, {%4,%5,%6,%7}, {%8,%9}, {%0,%1,%2,%3};"
        : "+f"(c0), "+f"(c1), "+f"(c2), "+f"(c3)
        : "r"(a0), "r"(a1), "r"(a2), "r"(a3), "r"(b0), "r"(b1));
}

#define LDSM_X4(R0,R1,R2,R3,ADDR) \
    asm volatile("ldmatrix.sync.aligned.m8n8.x4.shared.b16 {%0,%1,%2,%3}, [%4];" \
        : "=r"(R0), "=r"(R1), "=r"(R2), "=r"(R3) : "r"(ADDR))
#define LDSM_X4_T(R0,R1,R2,R3,ADDR) \
    asm volatile("ldmatrix.sync.aligned.m8n8.x4.trans.shared.b16 {%0,%1,%2,%3}, [%4];" \
        : "=r"(R0), "=r"(R1), "=r"(R2), "=r"(R3) : "r"(ADDR))

__device__ __forceinline__ uint32_t smem_u32(const void* p) {
    uint32_t a;
    asm("{ .reg .u64 t; cvta.to.shared.u64 t, %1; cvt.u32.u64 %0, t; }"
        : "=r"(a) : "l"(p));
    return a;
}

__device__ __forceinline__ uint32_t pack_f16x2(float a, float b) {
    __half2 h = __halves2half2(__float2half_rn(a), __float2half_rn(b));
    return *reinterpret_cast<uint32_t*>(&h);
}

// Convert one float4 -> 4 fp16, one 8 B store.
__device__ __forceinline__ void cvt_store4(uint32_t addr, float4 v) {
    uint32_t h01 = pack_f16x2(v.x, v.y);
    uint32_t h23 = pack_f16x2(v.z, v.w);
    asm volatile("st.shared.v2.u32 [%0], {%1,%2};" :: "r"(addr), "r"(h01), "r"(h23) : "memory");
}

// Smem (double-buffered, BK=16):
// A: [128 m][16 k] fp16, row 32 B pad 48 -> 6144 B/tile.  ldmatrix phase m*3 mod 8 distinct.
// B: [16 k][128 n] fp16, row 256 B pad 272 -> 4352 B/tile. ldmatrix.trans phase k*17 mod 8 distinct.
#define AROW   48
#define BROW   272
#define ABUF   6144
#define BBUF   4352
#define SM_A   0                 // 2 x 6144
#define SM_B   12288             // 2 x 4352
#define SM_TOT 20992             // well under 48 KB default

// ---------------------------------------------------------------------------
// V = Wv @ x_b + bv via mma.sync fp16 (single term, fp32 accumulate).
// BM=128, BN=128, BK=16, 256 thr, software-pipelined double buffer.
// ---------------------------------------------------------------------------
extern "C" __global__ void __launch_bounds__(256, 2)
gemm_v_mma(const float* __restrict__ x,
           const float* __restrict__ Wv,
           const float* __restrict__ bv,
           const float* __restrict__ gamma,
           float* __restrict__ out)
{
    extern __shared__ char sm[];
    const uint32_t sb = smem_u32(sm);
    const int tid  = threadIdx.x;
    const int wid  = tid >> 5;
    const int lane = tid & 31;
    const int g    = lane >> 2;
    const int t    = lane & 3;
    const int wm   = wid >> 1;         // warp m 0..3 (32 rows)
    const int wn   = wid & 1;          // warp n 0..1 (64 cols)

    const int bn = blockIdx.x;         // 0..15
    const int bm = blockIdx.y;         // 0..1
    const int bb = blockIdx.z;         // 0..7

    if (bn == 0 && bm == 0 && bb == 0 && tid == 0) g_bar = 0;

    float c[2][8][4];
#pragma unroll
    for (int mt = 0; mt < 2; mt++)
#pragma unroll
        for (int nt = 0; nt < 8; nt++)
#pragma unroll
            for (int q = 0; q < 4; q++) c[mt][nt][q] = 0.0f;

    const float* Ag = Wv + (size_t)(bm * 128) * CIN;
    const float* Bg = x + (size_t)bb * CIN * LL + bn * 128;

    // loader coordinates
    const int aRow = tid >> 2;                  // 0..63 (+64 on it=1)
    const int aP   = tid & 3;
    const int bK   = tid >> 5;                  // 0..7 (+8 on it=1)
    const int bP   = tid & 31;
    const uint32_t aOff = (uint32_t)(aRow * AROW + aP * 8);
    const uint32_t bOff = (uint32_t)(bK * BROW + bP * 8);

    // ldmatrix per-lane bases
    const int lane15  = lane & 15;
    const uint32_t aLaneOff = (uint32_t)((wm * 32 + lane15) * AROW + (lane >> 4) * 16);
    const int bKrow = ((lane >> 3) & 1) * 8 + (lane & 7);
    const uint32_t bLaneOff = (uint32_t)(bKrow * BROW + (wn * 64 + (lane >> 4) * 8) * 2);

    float4 pa[2], pb[2];

    // ---- prologue: load + convert chunk 0 into buffer 0 ----
#pragma unroll
    for (int it = 0; it < 2; it++) {
        pa[it] = *(const float4*)(Ag + (size_t)(aRow + it * 64) * CIN + aP * 4);
        pb[it] = *(const float4*)(Bg + (size_t)(bK + it * 8) * LL + bP * 4);
    }
#pragma unroll
    for (int it = 0; it < 2; it++) {
        cvt_store4(sb + SM_A + aOff + (uint32_t)(it * 64 * AROW), pa[it]);
        cvt_store4(sb + SM_B + bOff + (uint32_t)(it * 8 * BROW), pb[it]);
    }
    __syncthreads();

    for (int ch = 0; ch < 32; ch++) {
        const uint32_t abuf = (uint32_t)((ch & 1) * ABUF);
        const uint32_t bbuf = (uint32_t)((ch & 1) * BBUF);

        // next chunk's global loads first (latency hidden under mma)
        if (ch < 31) {
            const int k0 = (ch + 1) * 16;
#pragma unroll
            for (int it = 0; it < 2; it++) {
                pa[it] = *(const float4*)(Ag + (size_t)(aRow + it * 64) * CIN + k0 + aP * 4);
                pb[it] = *(const float4*)(Bg + (size_t)(k0 + bK + it * 8) * LL + bP * 4);
            }
        }

        // ---- compute: 16 mma ----
        {
            uint32_t Ah[2][4], Bf[4][4];

#pragma unroll
            for (int mt = 0; mt < 2; mt++)
                LDSM_X4(Ah[mt][0], Ah[mt][1], Ah[mt][2], Ah[mt][3],
                        sb + SM_A + abuf + aLaneOff + (uint32_t)(mt * 16 * AROW));
#pragma unroll
            for (int n2 = 0; n2 < 4; n2++)
                LDSM_X4_T(Bf[n2][0], Bf[n2][1], Bf[n2][2], Bf[n2][3],
                          sb + SM_B + bbuf + bLaneOff + (uint32_t)(n2 * 32));
#pragma unroll
            for (int mt = 0; mt < 2; mt++)
#pragma unroll
                for (int n2 = 0; n2 < 4; n2++) {
                    mma16816(c[mt][2*n2][0], c[mt][2*n2][1], c[mt][2*n2][2], c[mt][2*n2][3],
                             Ah[mt][0], Ah[mt][1], Ah[mt][2], Ah[mt][3],
                             Bf[n2][0], Bf[n2][1]);
                    mma16816(c[mt][2*n2+1][0], c[mt][2*n2+1][1], c[mt][2*n2+1][2], c[mt][2*n2+1][3],
                             Ah[mt][0], Ah[mt][1], Ah[mt][2], Ah[mt][3],
                             Bf[n2][2], Bf[n2][3]);
                }
        }

        // ---- convert + store next chunk into the other buffer ----
        if (ch < 31) {
            const uint32_t abuf2 = (uint32_t)(((ch + 1) & 1) * ABUF);
            const uint32_t bbuf2 = (uint32_t)(((ch + 1) & 1) * BBUF);
#pragma unroll
            for (int it = 0; it < 2; it++) {
                cvt_store4(sb + SM_A + abuf2 + aOff + (uint32_t)(it * 64 * AROW), pa[it]);
                cvt_store4(sb + SM_B + bbuf2 + bOff + (uint32_t)(it * 8 * BROW), pb[it]);
            }
        }
        __syncthreads();
    }

    // ---- epilogue ----
    const float gma = gamma[0];
    float* obase = out + (size_t)bb * (2 * CC) * LL;

#pragma unroll
    for (int mt = 0; mt < 2; mt++) {
        const int m0 = bm * 128 + wm * 32 + mt * 16 + g;
        const float bv0 = bv[m0];
        const float bv1 = bv[m0 + 8];
#pragma unroll
        for (int nt = 0; nt < 8; nt++) {
            const int l0 = bn * 128 + wn * 64 + nt * 8 + 2 * t;
            float2 r0 = make_float2(c[mt][nt][0] + bv0, c[mt][nt][1] + bv0);
            float2 r1 = make_float2(c[mt][nt][2] + bv1, c[mt][nt][3] + bv1);
            *(float2*)(obase + (size_t)(m0    ) * LL + l0) = r0;
            *(float2*)(obase + (size_t)(m0 + 8) * LL + l0) = r1;
            if (gma != 0.0f) {
                float* vs = g_V + (size_t)bb * CC * LL;
                *(float2*)(vs + (size_t)(m0    ) * LL + l0) = r0;
                *(float2*)(vs + (size_t)(m0 + 8) * LL + l0) = r1;
            } else {
                const float2 z = make_float2(0.f, 0.f);
                *(float2*)(obase + (size_t)(CC + m0    ) * LL + l0) = z;
                *(float2*)(obase + (size_t)(CC + m0 + 8) * LL + l0) = z;
            }
        }
    }
}

// ---------------------------------------------------------------------------
// Persistent guarded fallback (gamma != 0 only).
// ---------------------------------------------------------------------------
#define FB_GRID 64

__device__ void fb_bar(unsigned target) {
    __syncthreads();
    if (threadIdx.x == 0) {
        __threadfence();
        atomicAdd((unsigned*)&g_bar, 1u);
        while (g_bar < target) __nanosleep(200);
    }
    __syncthreads();
    __threadfence();
}

extern "C" __global__ void fallback_attn(
    const float* __restrict__ Wq, const float* __restrict__ bq,
    const float* __restrict__ Wk, const float* __restrict__ bk,
    const float* __restrict__ Wc, const float* __restrict__ bc,
    const float* __restrict__ gamma, float* __restrict__ out)
{
    const float g = gamma[0];
    if (g == 0.0f) return;

    const int nthr = FB_GRID * 256;
    const int gtid = blockIdx.x * 256 + threadIdx.x;

    {   // Q, K projections
        const size_t total = (size_t)BB * CC * LL;
        for (size_t w = gtid; w < total; w += nthr) {
            int l = (int)(w % LL);
            int o = (int)((w / LL) % CC);
            int b = (int)(w / ((size_t)CC * LL));
            float sq = bq[o], sk = bk[o];
            for (int cc = 0; cc < CC; cc++) {
                float vv = g_V[((size_t)b * CC + cc) * LL + l];
                sq = fmaf(Wq[o * CC + cc], vv, sq);
                sk = fmaf(Wk[o * CC + cc], vv, sk);
            }
            g_Q[w] = sq; g_K[w] = sk;
        }
    }
    fb_bar(1 * FB_GRID);

    {   // energy
        const size_t total = (size_t)BB * LL * LL;
        for (size_t w = gtid; w < total; w += nthr) {
            int j = (int)(w % LL);
            int i = (int)((w / LL) % LL);
            int b = (int)(w / ((size_t)LL * LL));
            float s = 0.0f;
            for (int cc = 0; cc < CC; cc++)
                s = fmaf(g_Q[((size_t)b * CC + cc) * LL + i],
                         g_K[((size_t)b * CC + cc) * LL + j], s);
            g_E[w] = s;
        }
    }
    fb_bar(2 * FB_GRID);

    {   // softmax rows (in place)
        __shared__ float red[256];
        const int tidl = threadIdx.x;
        for (int r = blockIdx.x; r < BB * LL; r += FB_GRID) {
            float* row = g_E + (size_t)r * LL;
            float mx = -INFINITY;
            for (int j = tidl; j < LL; j += 256) mx = fmaxf(mx, row[j]);
            red[tidl] = mx; __syncthreads();
            for (int s = 128; s > 0; s >>= 1) {
                if (tidl < s) red[tidl] = fmaxf(red[tidl], red[tidl + s]);
                __syncthreads();
            }
            mx = red[0]; __syncthreads();
            float sum = 0.0f;
            for (int j = tidl; j < LL; j += 256) {
                float e = expf(row[j] - mx);
                row[j] = e; sum += e;
            }
            red[tidl] = sum; __syncthreads();
            for (int s = 128; s > 0; s >>= 1) {
                if (tidl < s) red[tidl] += red[tidl + s];
                __syncthreads();
            }
            const float inv = 1.0f / red[0];
            __syncthreads();
            for (int j = tidl; j < LL; j += 256) row[j] *= inv;
            __syncthreads();
        }
    }
    fb_bar(3 * FB_GRID);

    {   // out_attn = V @ attn^T
        const size_t total = (size_t)BB * CC * LL;
        for (size_t w = gtid; w < total; w += nthr) {
            int i = (int)(w % LL);
            int cc = (int)((w / LL) % CC);
            int b = (int)(w / ((size_t)CC * LL));
            const float* vrow = g_V + ((size_t)b * CC + cc) * LL;
            const float* prow = g_E + ((size_t)b * LL + i) * LL;
            float s = 0.0f;
            for (int j = 0; j < LL; j++) s = fmaf(vrow[j], prow[j], s);
            g_O[((size_t)b * CC + cc) * LL + i] = s;
        }
    }
    fb_bar(4 * FB_GRID);

    {   // bottom half = gamma * (Wc @ O + bc)
        const size_t total = (size_t)BB * CC * LL;
        for (size_t w = gtid; w < total; w += nthr) {
            int l = (int)(w % LL);
            int o = (int)((w / LL) % CC);
            int b = (int)(w / ((size_t)CC * LL));
            float s = bc[o];
            for (int cc = 0; cc < CC; cc++)
                s = fmaf(Wc[o * CC + cc], g_O[((size_t)b * CC + cc) * LL + l], s);
            out[(size_t)b * (2 * CC) * LL + (size_t)(CC + o) * LL + l] = g * s;
        }
    }
}

// ---------------------------------------------------------------------------
extern "C" void kernel_launch(void* const* d_in, const int* in_sizes, int n_in,
                              void* d_out, int out_size)
{
    const float* x     = (const float*)d_in[0];
    const float* Wv    = (const float*)d_in[1];
    const float* bv    = (const float*)d_in[2];
    const float* Wq    = (const float*)d_in[3];
    const float* bq    = (const float*)d_in[4];
    const float* Wk    = (const float*)d_in[5];
    const float* bk    = (const float*)d_in[6];
    const float* Wc    = (const float*)d_in[7];
    const float* bc    = (const float*)d_in[8];
    const float* gamma = (const float*)d_in[9];
    float* out = (float*)d_out;

    dim3 grid(16, 2, 8);
    gemm_v_mma<<<grid, 256, SM_TOT>>>(x, Wv, bv, gamma, out);
    fallback_attn<<<FB_GRID, 256>>>(Wq, bq, Wk, bk, Wc, bc, gamma, out);
}

// round 11
// speedup vs baseline: 1.7503x; 1.0229x over previous
#include <cuda_runtime.h>
#include <cuda_fp16.h>
#include <cstdint>
#include <math.h>

#define BB   8
#define CIN  512
#define CC   256
#define LL   2048

#define NCTAS 256   // total grid; all resident (occ 2 x 148 SMs = 296 slots)

// ---------------------------------------------------------------------------
// Scratch for the gamma != 0 fallback path.
// ---------------------------------------------------------------------------
__device__ float g_V[BB * CC * LL];
__device__ float g_Q[BB * CC * LL];
__device__ float g_K[BB * CC * LL];
__device__ float g_O[BB * CC * LL];
__device__ float g_E[BB * LL * LL];
__device__ unsigned g_count = 0;   // self-resetting barrier state
__device__ unsigned g_sense = 0;

// ---------------------------------------------------------------------------
// mma.sync m16n8k16 fp16 + ldmatrix (sm_75/80 baseline — not arch-gated)
// ---------------------------------------------------------------------------
__device__ __forceinline__ void mma16816(float& c0, float& c1, float& c2, float& c3,
                                         uint32_t a0, uint32_t a1, uint32_t a2, uint32_t a3,
                                         uint32_t b0, uint32_t b1)
{
    asm volatile(
        "mma.sync.aligned.m16n8k16.row.col.f32.f16.f16.f32 "
        "{%0,%1,%2,%3}, {%4,%5,%6,%7}, {%8,%9}, {%0,%1,%2,%3};"
        : "+f"(c0), "+f"(c1), "+f"(c2), "+f"(c3)
        : "r"(a0), "r"(a1), "r"(a2), "r"(a3), "r"(b0), "r"(b1));
}

#define LDSM_X4(R0,R1,R2,R3,ADDR) \
    asm volatile("ldmatrix.sync.aligned.m8n8.x4.shared.b16 {%0,%1,%2,%3}, [%4];" \
        : "=r"(R0), "=r"(R1), "=r"(R2), "=r"(R3) : "r"(ADDR))
#define LDSM_X4_T(R0,R1,R2,R3,ADDR) \
    asm volatile("ldmatrix.sync.aligned.m8n8.x4.trans.shared.b16 {%0,%1,%2,%3}, [%4];" \
        : "=r"(R0), "=r"(R1), "=r"(R2), "=r"(R3) : "r"(ADDR))

__device__ __forceinline__ uint32_t smem_u32(const void* p) {
    uint32_t a;
    asm("{ .reg .u64 t; cvta.to.shared.u64 t, %1; cvt.u32.u64 %0, t; }"
        : "=r"(a) : "l"(p));
    return a;
}

__device__ __forceinline__ uint32_t pack_f16x2(float a, float b) {
    __half2 h = __halves2half2(__float2half_rn(a), __float2half_rn(b));
    return *reinterpret_cast<uint32_t*>(&h);
}

__device__ __forceinline__ void cvt_store4(uint32_t addr, float4 v) {
    uint32_t h01 = pack_f16x2(v.x, v.y);
    uint32_t h23 = pack_f16x2(v.z, v.w);
    asm volatile("st.shared.v2.u32 [%0], {%1,%2};" :: "r"(addr), "r"(h01), "r"(h23) : "memory");
}

// Self-resetting sense-reversing grid barrier. Safe across graph replays
// (counter always returns to 0; sense flips). Requires all NCTAS resident —
// guaranteed by __launch_bounds__(256, 2): 256 CTAs <= 296 slots.
__device__ void grid_bar() {
    __syncthreads();
    if (threadIdx.x == 0) {
        unsigned s = *(volatile unsigned*)&g_sense;
        __threadfence();
        if (atomicAdd(&g_count, 1u) == NCTAS - 1u) {
            g_count = 0;
            __threadfence();
            *(volatile unsigned*)&g_sense = s ^ 1u;
        } else {
            while (*(volatile unsigned*)&g_sense == s) __nanosleep(100);
        }
    }
    __syncthreads();
    __threadfence();
}

// Smem (double-buffered, BK=16):
// A: [128 m][16 k] fp16, row 32 B pad 48 -> 6144 B/tile.  ldmatrix phase m*3 mod 8 distinct.
// B: [16 k][128 n] fp16, row 256 B pad 272 -> 4352 B/tile. ldmatrix.trans phase k*17 mod 8 distinct.
#define AROW   48
#define BROW   272
#define ABUF   6144
#define BBUF   4352
#define SM_A   0
#define SM_B   12288
#define SM_TOT 20992

// ---------------------------------------------------------------------------
// Fallback attention phases (gamma != 0 only), run inside the fused kernel
// after grid_bar(). __noinline__ keeps them off the hot path's reg budget.
// ---------------------------------------------------------------------------
__device__ __noinline__ void fallback_phases(
    const float* __restrict__ Wq, const float* __restrict__ bq,
    const float* __restrict__ Wk, const float* __restrict__ bk,
    const float* __restrict__ Wc, const float* __restrict__ bc,
    float gma, float* __restrict__ out, float* red /*smem, 256 floats*/)
{
    const int nthr = NCTAS * 256;
    const int gtid = blockIdx.x * 256 + blockIdx.y * 256 * 16 +
                     blockIdx.z * 256 * 32 + threadIdx.x;   // unique over 256 CTAs
    const int cta  = blockIdx.x + blockIdx.y * 16 + blockIdx.z * 32;

    {   // Q, K projections
        const size_t total = (size_t)BB * CC * LL;
        for (size_t w = gtid; w < total; w += nthr) {
            int l = (int)(w % LL);
            int o = (int)((w / LL) % CC);
            int b = (int)(w / ((size_t)CC * LL));
            float sq = bq[o], sk = bk[o];
            for (int cc = 0; cc < CC; cc++) {
                float vv = g_V[((size_t)b * CC + cc) * LL + l];
                sq = fmaf(Wq[o * CC + cc], vv, sq);
                sk = fmaf(Wk[o * CC + cc], vv, sk);
            }
            g_Q[w] = sq; g_K[w] = sk;
        }
    }
    grid_bar();

    {   // energy
        const size_t total = (size_t)BB * LL * LL;
        for (size_t w = gtid; w < total; w += nthr) {
            int j = (int)(w % LL);
            int i = (int)((w / LL) % LL);
            int b = (int)(w / ((size_t)LL * LL));
            float s = 0.0f;
            for (int cc = 0; cc < CC; cc++)
                s = fmaf(g_Q[((size_t)b * CC + cc) * LL + i],
                         g_K[((size_t)b * CC + cc) * LL + j], s);
            g_E[w] = s;
        }
    }
    grid_bar();

    {   // softmax rows
        const int tidl = threadIdx.x;
        for (int r = cta; r < BB * LL; r += NCTAS) {
            float* row = g_E + (size_t)r * LL;
            float mx = -INFINITY;
            for (int j = tidl; j < LL; j += 256) mx = fmaxf(mx, row[j]);
            red[tidl] = mx; __syncthreads();
            for (int s = 128; s > 0; s >>= 1) {
                if (tidl < s) red[tidl] = fmaxf(red[tidl], red[tidl + s]);
                __syncthreads();
            }
            mx = red[0]; __syncthreads();
            float sum = 0.0f;
            for (int j = tidl; j < LL; j += 256) {
                float e = expf(row[j] - mx);
                row[j] = e; sum += e;
            }
            red[tidl] = sum; __syncthreads();
            for (int s = 128; s > 0; s >>= 1) {
                if (tidl < s) red[tidl] += red[tidl + s];
                __syncthreads();
            }
            const float inv = 1.0f / red[0];
            __syncthreads();
            for (int j = tidl; j < LL; j += 256) row[j] *= inv;
            __syncthreads();
        }
    }
    grid_bar();

    {   // out_attn = V @ attn^T
        const size_t total = (size_t)BB * CC * LL;
        for (size_t w = gtid; w < total; w += nthr) {
            int i = (int)(w % LL);
            int cc = (int)((w / LL) % CC);
            int b = (int)(w / ((size_t)CC * LL));
            const float* vrow = g_V + ((size_t)b * CC + cc) * LL;
            const float* prow = g_E + ((size_t)b * LL + i) * LL;
            float s = 0.0f;
            for (int j = 0; j < LL; j++) s = fmaf(vrow[j], prow[j], s);
            g_O[((size_t)b * CC + cc) * LL + i] = s;
        }
    }
    grid_bar();

    {   // bottom half = gamma * (Wc @ O + bc)
        const size_t total = (size_t)BB * CC * LL;
        for (size_t w = gtid; w < total; w += nthr) {
            int l = (int)(w % LL);
            int o = (int)((w / LL) % CC);
            int b = (int)(w / ((size_t)CC * LL));
            float s = bc[o];
            for (int cc = 0; cc < CC; cc++)
                s = fmaf(Wc[o * CC + cc], g_O[((size_t)b * CC + cc) * LL + l], s);
            out[(size_t)b * (2 * CC) * LL + (size_t)(CC + o) * LL + l] = gma * s;
        }
    }
}

// ---------------------------------------------------------------------------
// Fused kernel: V-GEMM (mma.sync fp16, fp32 accum) + epilogue; when gamma!=0,
// grid-barrier then full attention fallback. Single launch, one graph node.
// ---------------------------------------------------------------------------
extern "C" __global__ void __launch_bounds__(256, 2)
fused_attn_conv(const float* __restrict__ x,
                const float* __restrict__ Wv,
                const float* __restrict__ bv,
                const float* __restrict__ Wq, const float* __restrict__ bq,
                const float* __restrict__ Wk, const float* __restrict__ bk,
                const float* __restrict__ Wc, const float* __restrict__ bc,
                const float* __restrict__ gamma,
                float* __restrict__ out)
{
    extern __shared__ char sm[];
    const uint32_t sb = smem_u32(sm);
    const int tid  = threadIdx.x;
    const int wid  = tid >> 5;
    const int lane = tid & 31;
    const int g    = lane >> 2;
    const int t    = lane & 3;
    const int wm   = wid >> 1;
    const int wn   = wid & 1;

    const int bn = blockIdx.x;         // 0..15
    const int bm = blockIdx.y;         // 0..1
    const int bb = blockIdx.z;         // 0..7

    float c[2][8][4];
#pragma unroll
    for (int mt = 0; mt < 2; mt++)
#pragma unroll
        for (int nt = 0; nt < 8; nt++)
#pragma unroll
            for (int q = 0; q < 4; q++) c[mt][nt][q] = 0.0f;

    const float* Ag = Wv + (size_t)(bm * 128) * CIN;
    const float* Bg = x + (size_t)bb * CIN * LL + bn * 128;

    const int aRow = tid >> 2;
    const int aP   = tid & 3;
    const int bK   = tid >> 5;
    const int bP   = tid & 31;
    const uint32_t aOff = (uint32_t)(aRow * AROW + aP * 8);
    const uint32_t bOff = (uint32_t)(bK * BROW + bP * 8);

    const int lane15  = lane & 15;
    const uint32_t aLaneOff = (uint32_t)((wm * 32 + lane15) * AROW + (lane >> 4) * 16);
    const int bKrow = ((lane >> 3) & 1) * 8 + (lane & 7);
    const uint32_t bLaneOff = (uint32_t)(bKrow * BROW + (wn * 64 + (lane >> 4) * 8) * 2);

    float4 pa[2], pb[2];

    // prologue
#pragma unroll
    for (int it = 0; it < 2; it++) {
        pa[it] = *(const float4*)(Ag + (size_t)(aRow + it * 64) * CIN + aP * 4);
        pb[it] = *(const float4*)(Bg + (size_t)(bK + it * 8) * LL + bP * 4);
    }
#pragma unroll
    for (int it = 0; it < 2; it++) {
        cvt_store4(sb + SM_A + aOff + (uint32_t)(it * 64 * AROW), pa[it]);
        cvt_store4(sb + SM_B + bOff + (uint32_t)(it * 8 * BROW), pb[it]);
    }
    __syncthreads();

    for (int ch = 0; ch < 32; ch++) {
        const uint32_t abuf = (uint32_t)((ch & 1) * ABUF);
        const uint32_t bbuf = (uint32_t)((ch & 1) * BBUF);

        if (ch < 31) {
            const int k0 = (ch + 1) * 16;
#pragma unroll
            for (int it = 0; it < 2; it++) {
                pa[it] = *(const float4*)(Ag + (size_t)(aRow + it * 64) * CIN + k0 + aP * 4);
                pb[it] = *(const float4*)(Bg + (size_t)(k0 + bK + it * 8) * LL + bP * 4);
            }
        }

        {
            uint32_t Ah[2][4], Bf[4][4];
#pragma unroll
            for (int mt = 0; mt < 2; mt++)
                LDSM_X4(Ah[mt][0], Ah[mt][1], Ah[mt][2], Ah[mt][3],
                        sb + SM_A + abuf + aLaneOff + (uint32_t)(mt * 16 * AROW));
#pragma unroll
            for (int n2 = 0; n2 < 4; n2++)
                LDSM_X4_T(Bf[n2][0], Bf[n2][1], Bf[n2][2], Bf[n2][3],
                          sb + SM_B + bbuf + bLaneOff + (uint32_t)(n2 * 32));
#pragma unroll
            for (int mt = 0; mt < 2; mt++)
#pragma unroll
                for (int n2 = 0; n2 < 4; n2++) {
                    mma16816(c[mt][2*n2][0], c[mt][2*n2][1], c[mt][2*n2][2], c[mt][2*n2][3],
                             Ah[mt][0], Ah[mt][1], Ah[mt][2], Ah[mt][3],
                             Bf[n2][0], Bf[n2][1]);
                    mma16816(c[mt][2*n2+1][0], c[mt][2*n2+1][1], c[mt][2*n2+1][2], c[mt][2*n2+1][3],
                             Ah[mt][0], Ah[mt][1], Ah[mt][2], Ah[mt][3],
                             Bf[n2][2], Bf[n2][3]);
                }
        }

        if (ch < 31) {
            const uint32_t abuf2 = (uint32_t)(((ch + 1) & 1) * ABUF);
            const uint32_t bbuf2 = (uint32_t)(((ch + 1) & 1) * BBUF);
#pragma unroll
            for (int it = 0; it < 2; it++) {
                cvt_store4(sb + SM_A + abuf2 + aOff + (uint32_t)(it * 64 * AROW), pa[it]);
                cvt_store4(sb + SM_B + bbuf2 + bOff + (uint32_t)(it * 8 * BROW), pb[it]);
            }
        }
        __syncthreads();
    }

    // ---- epilogue ----
    const float gma = gamma[0];
    float* obase = out + (size_t)bb * (2 * CC) * LL;

#pragma unroll
    for (int mt = 0; mt < 2; mt++) {
        const int m0 = bm * 128 + wm * 32 + mt * 16 + g;
        const float bv0 = bv[m0];
        const float bv1 = bv[m0 + 8];
#pragma unroll
        for (int nt = 0; nt < 8; nt++) {
            const int l0 = bn * 128 + wn * 64 + nt * 8 + 2 * t;
            float2 r0 = make_float2(c[mt][nt][0] + bv0, c[mt][nt][1] + bv0);
            float2 r1 = make_float2(c[mt][nt][2] + bv1, c[mt][nt][3] + bv1);
            *(float2*)(obase + (size_t)(m0    ) * LL + l0) = r0;
            *(float2*)(obase + (size_t)(m0 + 8) * LL + l0) = r1;
            if (gma != 0.0f) {
                float* vs = g_V + (size_t)bb * CC * LL;
                *(float2*)(vs + (size_t)(m0    ) * LL + l0) = r0;
                *(float2*)(vs + (size_t)(m0 + 8) * LL + l0) = r1;
            } else {
                const float2 z = make_float2(0.f, 0.f);
                *(float2*)(obase + (size_t)(CC + m0    ) * LL + l0) = z;
                *(float2*)(obase + (size_t)(CC + m0 + 8) * LL + l0) = z;
            }
        }
    }

    // ---- gamma != 0: run attention fallback in this same launch ----
    if (gma != 0.0f) {
        grid_bar();   // g_V complete across the grid
        fallback_phases(Wq, bq, Wk, bk, Wc, bc, gma, out, (float*)sm);
    }
}

// ---------------------------------------------------------------------------
extern "C" void kernel_launch(void* const* d_in, const int* in_sizes, int n_in,
                              void* d_out, int out_size)
{
    const float* x     = (const float*)d_in[0];
    const float* Wv    = (const float*)d_in[1];
    const float* bv    = (const float*)d_in[2];
    const float* Wq    = (const float*)d_in[3];
    const float* bq    = (const float*)d_in[4];
    const float* Wk    = (const float*)d_in[5];
    const float* bk    = (const float*)d_in[6];
    const float* Wc    = (const float*)d_in[7];
    const float* bc    = (const float*)d_in[8];
    const float* gamma = (const float*)d_in[9];
    float* out = (float*)d_out;

    dim3 grid(16, 2, 8);   // 256 CTAs, all resident at occ 2
    fused_attn_conv<<<grid, 256, SM_TOT>>>(x, Wv, bv, Wq, bq, Wk, bk,
                                           Wc, bc, gamma, out);
}

// round 12
// speedup vs baseline: 1.7521x; 1.0010x over previous
#include <cuda_runtime.h>
#include <cuda_fp16.h>
#include <cstdint>
#include <math.h>

#define BB   8
#define CIN  512
#define CC   256
#define LL   2048

#define NCTAS 256   // all resident: occ 2 x 148 SMs = 296 slots

// ---------------------------------------------------------------------------
// Scratch for the gamma != 0 fallback path.
// ---------------------------------------------------------------------------
__device__ float g_V[BB * CC * LL];
__device__ float g_Q[BB * CC * LL];
__device__ float g_K[BB * CC * LL];
__device__ float g_O[BB * CC * LL];
__device__ float g_E[BB * LL * LL];
__device__ unsigned g_count = 0;   // self-resetting barrier state
__device__ unsigned g_sense = 0;

// ---------------------------------------------------------------------------
// mma.sync m16n8k16 fp16 + ldmatrix (sm_75/80 baseline — not arch-gated)
// ---------------------------------------------------------------------------
__device__ __forceinline__ void mma16816(float& c0, float& c1, float& c2, float& c3,
                                         uint32_t a0, uint32_t a1, uint32_t a2, uint32_t a3,
                                         uint32_t b0, uint32_t b1)
{
    asm volatile(
        "mma.sync.aligned.m16n8k16.row.col.f32.f16.f16.f32 "
        "{%0,%1,%2,%3}, {%4,%5,%6,%7}, {%8,%9}, {%0,%1,%2,%3};"
        : "+f"(c0), "+f"(c1), "+f"(c2), "+f"(c3)
        : "r"(a0), "r"(a1), "r"(a2), "r"(a3), "r"(b0), "r"(b1));
}

#define LDSM_X4(R0,R1,R2,R3,ADDR) \
    asm volatile("ldmatrix.sync.aligned.m8n8.x4.shared.b16 {%0,%1,%2,%3}, [%4];" \
        : "=r"(R0), "=r"(R1), "=r"(R2), "=r"(R3) : "r"(ADDR))
#define LDSM_X4_T(R0,R1,R2,R3,ADDR) \
    asm volatile("ldmatrix.sync.aligned.m8n8.x4.trans.shared.b16 {%0,%1,%2,%3}, [%4];" \
        : "=r"(R0), "=r"(R1), "=r"(R2), "=r"(R3) : "r"(ADDR))

__device__ __forceinline__ uint32_t smem_u32(const void* p) {
    uint32_t a;
    asm("{ .reg .u64 t; cvta.to.shared.u64 t, %1; cvt.u32.u64 %0, t; }"
        : "=r"(a) : "l"(p));
    return a;
}

__device__ __forceinline__ uint32_t pack_f16x2(float a, float b) {
    __half2 h = __halves2half2(__float2half_rn(a), __float2half_rn(b));
    return *reinterpret_cast<uint32_t*>(&h);
}

__device__ __forceinline__ void cvt_store4(uint32_t addr, float4 v) {
    uint32_t h01 = pack_f16x2(v.x, v.y);
    uint32_t h23 = pack_f16x2(v.z, v.w);
    asm volatile("st.shared.v2.u32 [%0], {%1,%2};" :: "r"(addr), "r"(h01), "r"(h23) : "memory");
}

// Self-resetting sense-reversing grid barrier (all NCTAS resident).
__device__ void grid_bar() {
    __syncthreads();
    if (threadIdx.x == 0) {
        unsigned s = *(volatile unsigned*)&g_sense;
        __threadfence();
        if (atomicAdd(&g_count, 1u) == NCTAS - 1u) {
            g_count = 0;
            __threadfence();
            *(volatile unsigned*)&g_sense = s ^ 1u;
        } else {
            while (*(volatile unsigned*)&g_sense == s) __nanosleep(100);
        }
    }
    __syncthreads();
    __threadfence();
}

// Smem (double-buffered, BK=16):
// A: [128 m][16 k] fp16, row 32 B pad 48 -> 6144 B/tile.  ldmatrix phase m*3 mod 8 distinct.
// B: [16 k][128 n] fp16, row 256 B pad 272 -> 4352 B/tile. ldmatrix.trans phase k*17 mod 8 distinct.
#define AROW   48
#define BROW   272
#define ABUF   6144
#define BBUF   4352
#define SM_A   0
#define SM_B   12288
#define SM_TOT 20992

// ---------------------------------------------------------------------------
// Fallback attention phases (gamma != 0 only).
// ---------------------------------------------------------------------------
__device__ __noinline__ void fallback_phases(
    const float* __restrict__ Wq, const float* __restrict__ bq,
    const float* __restrict__ Wk, const float* __restrict__ bk,
    const float* __restrict__ Wc, const float* __restrict__ bc,
    float gma, float* __restrict__ out, float* red /*smem, 256 floats*/)
{
    const int nthr = NCTAS * 256;
    const int cta  = blockIdx.x + blockIdx.y * 16 + blockIdx.z * 32;
    const int gtid = cta * 256 + threadIdx.x;

    {   // Q, K projections
        const size_t total = (size_t)BB * CC * LL;
        for (size_t w = gtid; w < total; w += nthr) {
            int l = (int)(w % LL);
            int o = (int)((w / LL) % CC);
            int b = (int)(w / ((size_t)CC * LL));
            float sq = bq[o], sk = bk[o];
            for (int cc = 0; cc < CC; cc++) {
                float vv = g_V[((size_t)b * CC + cc) * LL + l];
                sq = fmaf(Wq[o * CC + cc], vv, sq);
                sk = fmaf(Wk[o * CC + cc], vv, sk);
            }
            g_Q[w] = sq; g_K[w] = sk;
        }
    }
    grid_bar();

    {   // energy
        const size_t total = (size_t)BB * LL * LL;
        for (size_t w = gtid; w < total; w += nthr) {
            int j = (int)(w % LL);
            int i = (int)((w / LL) % LL);
            int b = (int)(w / ((size_t)LL * LL));
            float s = 0.0f;
            for (int cc = 0; cc < CC; cc++)
                s = fmaf(g_Q[((size_t)b * CC + cc) * LL + i],
                         g_K[((size_t)b * CC + cc) * LL + j], s);
            g_E[w] = s;
        }
    }
    grid_bar();

    {   // softmax rows
        const int tidl = threadIdx.x;
        for (int r = cta; r < BB * LL; r += NCTAS) {
            float* row = g_E + (size_t)r * LL;
            float mx = -INFINITY;
            for (int j = tidl; j < LL; j += 256) mx = fmaxf(mx, row[j]);
            red[tidl] = mx; __syncthreads();
            for (int s = 128; s > 0; s >>= 1) {
                if (tidl < s) red[tidl] = fmaxf(red[tidl], red[tidl + s]);
                __syncthreads();
            }
            mx = red[0]; __syncthreads();
            float sum = 0.0f;
            for (int j = tidl; j < LL; j += 256) {
                float e = expf(row[j] - mx);
                row[j] = e; sum += e;
            }
            red[tidl] = sum; __syncthreads();
            for (int s = 128; s > 0; s >>= 1) {
                if (tidl < s) red[tidl] += red[tidl + s];
                __syncthreads();
            }
            const float inv = 1.0f / red[0];
            __syncthreads();
            for (int j = tidl; j < LL; j += 256) row[j] *= inv;
            __syncthreads();
        }
    }
    grid_bar();

    {   // out_attn = V @ attn^T
        const size_t total = (size_t)BB * CC * LL;
        for (size_t w = gtid; w < total; w += nthr) {
            int i = (int)(w % LL);
            int cc = (int)((w / LL) % CC);
            int b = (int)(w / ((size_t)CC * LL));
            const float* vrow = g_V + ((size_t)b * CC + cc) * LL;
            const float* prow = g_E + ((size_t)b * LL + i) * LL;
            float s = 0.0f;
            for (int j = 0; j < LL; j++) s = fmaf(vrow[j], prow[j], s);
            g_O[((size_t)b * CC + cc) * LL + i] = s;
        }
    }
    grid_bar();

    {   // bottom half = gamma * (Wc @ O + bc)
        const size_t total = (size_t)BB * CC * LL;
        for (size_t w = gtid; w < total; w += nthr) {
            int l = (int)(w % LL);
            int o = (int)((w / LL) % CC);
            int b = (int)(w / ((size_t)CC * LL));
            float s = bc[o];
            for (int cc = 0; cc < CC; cc++)
                s = fmaf(Wc[o * CC + cc], g_O[((size_t)b * CC + cc) * LL + l], s);
            out[(size_t)b * (2 * CC) * LL + (size_t)(CC + o) * LL + l] = gma * s;
        }
    }
}

// ---------------------------------------------------------------------------
// Fused kernel. Main-loop schedule per iter ch:
//   STS(ch+1)   [regs loaded last iter -> other buffer; drains under compute]
//   LDG(ch+2)   [full iteration of latency cover; x is L2-resident]
//   compute(ch) [16 mma from buf ch&1]
//   __syncthreads()
// ---------------------------------------------------------------------------
extern "C" __global__ void __launch_bounds__(256, 2)
fused_attn_conv(const float* __restrict__ x,
                const float* __restrict__ Wv,
                const float* __restrict__ bv,
                const float* __restrict__ Wq, const float* __restrict__ bq,
                const float* __restrict__ Wk, const float* __restrict__ bk,
                const float* __restrict__ Wc, const float* __restrict__ bc,
                const float* __restrict__ gamma,
                float* __restrict__ out)
{
    extern __shared__ char sm[];
    const uint32_t sb = smem_u32(sm);
    const int tid  = threadIdx.x;
    const int wid  = tid >> 5;
    const int lane = tid & 31;
    const int g    = lane >> 2;
    const int t    = lane & 3;
    const int wm   = wid >> 1;
    const int wn   = wid & 1;

    const int bn = blockIdx.x;         // 0..15
    const int bm = blockIdx.y;         // 0..1
    const int bb = blockIdx.z;         // 0..7

    float c[2][8][4];
#pragma unroll
    for (int mt = 0; mt < 2; mt++)
#pragma unroll
        for (int nt = 0; nt < 8; nt++)
#pragma unroll
            for (int q = 0; q < 4; q++) c[mt][nt][q] = 0.0f;

    const float* Ag = Wv + (size_t)(bm * 128) * CIN;
    const float* Bg = x + (size_t)bb * CIN * LL + bn * 128;

    const int aRow = tid >> 2;
    const int aP   = tid & 3;
    const int bK   = tid >> 5;
    const int bP   = tid & 31;
    const uint32_t aOff = (uint32_t)(aRow * AROW + aP * 8);
    const uint32_t bOff = (uint32_t)(bK * BROW + bP * 8);

    const int lane15  = lane & 15;
    const uint32_t aLaneOff = (uint32_t)((wm * 32 + lane15) * AROW + (lane >> 4) * 16);
    const int bKrow = ((lane >> 3) & 1) * 8 + (lane & 7);
    const uint32_t bLaneOff = (uint32_t)(bKrow * BROW + (wn * 64 + (lane >> 4) * 8) * 2);

    float4 pa[2], pb[2];

    // ---- prologue: chunk 0 into buf0; prefetch chunk 1 into regs ----
#pragma unroll
    for (int it = 0; it < 2; it++) {
        pa[it] = *(const float4*)(Ag + (size_t)(aRow + it * 64) * CIN + aP * 4);
        pb[it] = *(const float4*)(Bg + (size_t)(bK + it * 8) * LL + bP * 4);
    }
#pragma unroll
    for (int it = 0; it < 2; it++) {
        cvt_store4(sb + SM_A + aOff + (uint32_t)(it * 64 * AROW), pa[it]);
        cvt_store4(sb + SM_B + bOff + (uint32_t)(it * 8 * BROW), pb[it]);
    }
#pragma unroll
    for (int it = 0; it < 2; it++) {
        pa[it] = *(const float4*)(Ag + (size_t)(aRow + it * 64) * CIN + 16 + aP * 4);
        pb[it] = *(const float4*)(Bg + (size_t)(16 + bK + it * 8) * LL + bP * 4);
    }
    __syncthreads();

    for (int ch = 0; ch < 32; ch++) {
        const uint32_t abuf = (uint32_t)((ch & 1) * ABUF);
        const uint32_t bbuf = (uint32_t)((ch & 1) * BBUF);

        // STS chunk ch+1 (regs loaded last iteration) into the other buffer.
        if (ch < 31) {
            const uint32_t abuf2 = (uint32_t)(((ch + 1) & 1) * ABUF);
            const uint32_t bbuf2 = (uint32_t)(((ch + 1) & 1) * BBUF);
#pragma unroll
            for (int it = 0; it < 2; it++) {
                cvt_store4(sb + SM_A + abuf2 + aOff + (uint32_t)(it * 64 * AROW), pa[it]);
                cvt_store4(sb + SM_B + bbuf2 + bOff + (uint32_t)(it * 8 * BROW), pb[it]);
            }
        }
        // LDG chunk ch+2 into regs (consumed top of next iter).
        if (ch < 30) {
            const int k0 = (ch + 2) * 16;
#pragma unroll
            for (int it = 0; it < 2; it++) {
                pa[it] = *(const float4*)(Ag + (size_t)(aRow + it * 64) * CIN + k0 + aP * 4);
                pb[it] = *(const float4*)(Bg + (size_t)(k0 + bK + it * 8) * LL + bP * 4);
            }
        }

        // compute chunk ch
        {
            uint32_t Ah[2][4], Bf[4][4];
#pragma unroll
            for (int mt = 0; mt < 2; mt++)
                LDSM_X4(Ah[mt][0], Ah[mt][1], Ah[mt][2], Ah[mt][3],
                        sb + SM_A + abuf + aLaneOff + (uint32_t)(mt * 16 * AROW));
#pragma unroll
            for (int n2 = 0; n2 < 4; n2++)
                LDSM_X4_T(Bf[n2][0], Bf[n2][1], Bf[n2][2], Bf[n2][3],
                          sb + SM_B + bbuf + bLaneOff + (uint32_t)(n2 * 32));
#pragma unroll
            for (int mt = 0; mt < 2; mt++)
#pragma unroll
                for (int n2 = 0; n2 < 4; n2++) {
                    mma16816(c[mt][2*n2][0], c[mt][2*n2][1], c[mt][2*n2][2], c[mt][2*n2][3],
                             Ah[mt][0], Ah[mt][1], Ah[mt][2], Ah[mt][3],
                             Bf[n2][0], Bf[n2][1]);
                    mma16816(c[mt][2*n2+1][0], c[mt][2*n2+1][1], c[mt][2*n2+1][2], c[mt][2*n2+1][3],
                             Ah[mt][0], Ah[mt][1], Ah[mt][2], Ah[mt][3],
                             Bf[n2][2], Bf[n2][3]);
                }
        }
        __syncthreads();
    }

    // ---- epilogue: top half (+bias); g_V mirror only when gamma != 0 ----
    const float gma = gamma[0];
    float* obase = out + (size_t)bb * (2 * CC) * LL;

#pragma unroll
    for (int mt = 0; mt < 2; mt++) {
        const int m0 = bm * 128 + wm * 32 + mt * 16 + g;
        const float bv0 = bv[m0];
        const float bv1 = bv[m0 + 8];
#pragma unroll
        for (int nt = 0; nt < 8; nt++) {
            const int l0 = bn * 128 + wn * 64 + nt * 8 + 2 * t;
            float2 r0 = make_float2(c[mt][nt][0] + bv0, c[mt][nt][1] + bv0);
            float2 r1 = make_float2(c[mt][nt][2] + bv1, c[mt][nt][3] + bv1);
            *(float2*)(obase + (size_t)(m0    ) * LL + l0) = r0;
            *(float2*)(obase + (size_t)(m0 + 8) * LL + l0) = r1;
            if (gma != 0.0f) {
                float* vs = g_V + (size_t)bb * CC * LL;
                *(float2*)(vs + (size_t)(m0    ) * LL + l0) = r0;
                *(float2*)(vs + (size_t)(m0 + 8) * LL + l0) = r1;
            }
        }
    }

    if (gma == 0.0f) {
        // Coalesced zero fill of the mirror tile: 128 rows x 128 cols fp32.
        float* zbase = obase + (size_t)(CC + bm * 128) * LL + bn * 128;
        const float4 z = make_float4(0.f, 0.f, 0.f, 0.f);
#pragma unroll
        for (int i = 0; i < 16; i++) {
            int idx = i * 256 + tid;       // 4096 float4 = 64 KB
            int r   = idx >> 5;            // 0..127
            int cq  = idx & 31;            // 0..31
            *(float4*)(zbase + (size_t)r * LL + cq * 4) = z;
        }
    } else {
        grid_bar();   // g_V complete across the grid
        fallback_phases(Wq, bq, Wk, bk, Wc, bc, gma, out, (float*)sm);
    }
}

// ---------------------------------------------------------------------------
extern "C" void kernel_launch(void* const* d_in, const int* in_sizes, int n_in,
                              void* d_out, int out_size)
{
    const float* x     = (const float*)d_in[0];
    const float* Wv    = (const float*)d_in[1];
    const float* bv    = (const float*)d_in[2];
    const float* Wq    = (const float*)d_in[3];
    const float* bq    = (const float*)d_in[4];
    const float* Wk    = (const float*)d_in[5];
    const float* bk    = (const float*)d_in[6];
    const float* Wc    = (const float*)d_in[7];
    const float* bc    = (const float*)d_in[8];
    const float* gamma = (const float*)d_in[9];
    float* out = (float*)d_out;

    dim3 grid(16, 2, 8);   // 256 CTAs, all resident at occ 2
    fused_attn_conv<<<grid, 256, SM_TOT>>>(x, Wv, bv, Wq, bq, Wk, bk,
                                           Wc, bc, gamma, out);
}

// round 13
// speedup vs baseline: 1.8342x; 1.0469x over previous
#include <cuda_runtime.h>
#include <cuda_fp16.h>
#include <cstdint>
#include <math.h>

#define BB   8
#define CIN  512
#define CC   256
#define LL   2048

#define NCTAS 256   // all resident: occ 2 x 148 SMs = 296 slots

// ---------------------------------------------------------------------------
// Scratch for the gamma != 0 fallback path.
// ---------------------------------------------------------------------------
__device__ float g_V[BB * CC * LL];
__device__ float g_Q[BB * CC * LL];
__device__ float g_K[BB * CC * LL];
__device__ float g_O[BB * CC * LL];
__device__ float g_E[BB * LL * LL];
__device__ unsigned g_count = 0;   // self-resetting barrier state
__device__ unsigned g_sense = 0;

// ---------------------------------------------------------------------------
// mma.sync m16n8k16 fp16 + ldmatrix (sm_75/80 baseline — not arch-gated)
// ---------------------------------------------------------------------------
__device__ __forceinline__ void mma16816(float& c0, float& c1, float& c2, float& c3,
                                         uint32_t a0, uint32_t a1, uint32_t a2, uint32_t a3,
                                         uint32_t b0, uint32_t b1)
{
    asm volatile(
        "mma.sync.aligned.m16n8k16.row.col.f32.f16.f16.f32 "
        "{%0,%1,%2,%3}, {%4,%5,%6,%7}, {%8,%9}, {%0,%1,%2,%3};"
        : "+f"(c0), "+f"(c1), "+f"(c2), "+f"(c3)
        : "r"(a0), "r"(a1), "r"(a2), "r"(a3), "r"(b0), "r"(b1));
}

#define LDSM_X4(R0,R1,R2,R3,ADDR) \
    asm volatile("ldmatrix.sync.aligned.m8n8.x4.shared.b16 {%0,%1,%2,%3}, [%4];" \
        : "=r"(R0), "=r"(R1), "=r"(R2), "=r"(R3) : "r"(ADDR))
#define LDSM_X4_T(R0,R1,R2,R3,ADDR) \
    asm volatile("ldmatrix.sync.aligned.m8n8.x4.trans.shared.b16 {%0,%1,%2,%3}, [%4];" \
        : "=r"(R0), "=r"(R1), "=r"(R2), "=r"(R3) : "r"(ADDR))

__device__ __forceinline__ uint32_t smem_u32(const void* p) {
    uint32_t a;
    asm("{ .reg .u64 t; cvta.to.shared.u64 t, %1; cvt.u32.u64 %0, t; }"
        : "=r"(a) : "l"(p));
    return a;
}

__device__ __forceinline__ uint32_t pack_f16x2(float a, float b) {
    __half2 h = __halves2half2(__float2half_rn(a), __float2half_rn(b));
    return *reinterpret_cast<uint32_t*>(&h);
}

__device__ __forceinline__ void cvt_store4(uint32_t addr, float4 v) {
    uint32_t h01 = pack_f16x2(v.x, v.y);
    uint32_t h23 = pack_f16x2(v.z, v.w);
    asm volatile("st.shared.v2.u32 [%0], {%1,%2};" :: "r"(addr), "r"(h01), "r"(h23) : "memory");
}

// Self-resetting sense-reversing grid barrier (all NCTAS resident).
__device__ void grid_bar() {
    __syncthreads();
    if (threadIdx.x == 0) {
        unsigned s = *(volatile unsigned*)&g_sense;
        __threadfence();
        if (atomicAdd(&g_count, 1u) == NCTAS - 1u) {
            g_count = 0;
            __threadfence();
            *(volatile unsigned*)&g_sense = s ^ 1u;
        } else {
            while (*(volatile unsigned*)&g_sense == s) __nanosleep(100);
        }
    }
    __syncthreads();
    __threadfence();
}

// Smem: 4-stage pipeline, BK=16 per stage.
// A: [128 m][16 k] fp16, row 32 B pad 48 -> 6144 B.  ldmatrix phase m*3 mod 8 distinct.
// B: [16 k][128 n] fp16, row 256 B pad 272 -> 4352 B. ldmatrix.trans phase k*17 mod 8 distinct.
// Stage s at s*STAGE; A at +0, B at +6144.
#define AROW   48
#define BROW   272
#define STAGE  10496            // 6144 + 4352
#define SM_TOT 41984            // 4 stages < 48 KB default
//
// Sync-every-2 safety (4 stages): at iter ch we read buf ch%4 (written at
// ch-2, before the barrier ending iter ch-1 when ch even / the one ending
// ch-3 when odd) and write buf (ch+2)%4 (last read at ch-2, also pre-barrier).
// Reuse distance 2 on both edges -> one __syncthreads per 2 iters suffices.

// ---------------------------------------------------------------------------
// Fallback attention phases (gamma != 0 only).
// ---------------------------------------------------------------------------
__device__ __noinline__ void fallback_phases(
    const float* __restrict__ Wq, const float* __restrict__ bq,
    const float* __restrict__ Wk, const float* __restrict__ bk,
    const float* __restrict__ Wc, const float* __restrict__ bc,
    float gma, float* __restrict__ out, float* red /*smem, 256 floats*/)
{
    const int nthr = NCTAS * 256;
    const int cta  = blockIdx.x + blockIdx.y * 16 + blockIdx.z * 32;
    const int gtid = cta * 256 + threadIdx.x;

    {   // Q, K projections
        const size_t total = (size_t)BB * CC * LL;
        for (size_t w = gtid; w < total; w += nthr) {
            int l = (int)(w % LL);
            int o = (int)((w / LL) % CC);
            int b = (int)(w / ((size_t)CC * LL));
            float sq = bq[o], sk = bk[o];
            for (int cc = 0; cc < CC; cc++) {
                float vv = g_V[((size_t)b * CC + cc) * LL + l];
                sq = fmaf(Wq[o * CC + cc], vv, sq);
                sk = fmaf(Wk[o * CC + cc], vv, sk);
            }
            g_Q[w] = sq; g_K[w] = sk;
        }
    }
    grid_bar();

    {   // energy
        const size_t total = (size_t)BB * LL * LL;
        for (size_t w = gtid; w < total; w += nthr) {
            int j = (int)(w % LL);
            int i = (int)((w / LL) % LL);
            int b = (int)(w / ((size_t)LL * LL));
            float s = 0.0f;
            for (int cc = 0; cc < CC; cc++)
                s = fmaf(g_Q[((size_t)b * CC + cc) * LL + i],
                         g_K[((size_t)b * CC + cc) * LL + j], s);
            g_E[w] = s;
        }
    }
    grid_bar();

    {   // softmax rows
        const int tidl = threadIdx.x;
        for (int r = cta; r < BB * LL; r += NCTAS) {
            float* row = g_E + (size_t)r * LL;
            float mx = -INFINITY;
            for (int j = tidl; j < LL; j += 256) mx = fmaxf(mx, row[j]);
            red[tidl] = mx; __syncthreads();
            for (int s = 128; s > 0; s >>= 1) {
                if (tidl < s) red[tidl] = fmaxf(red[tidl], red[tidl + s]);
                __syncthreads();
            }
            mx = red[0]; __syncthreads();
            float sum = 0.0f;
            for (int j = tidl; j < LL; j += 256) {
                float e = expf(row[j] - mx);
                row[j] = e; sum += e;
            }
            red[tidl] = sum; __syncthreads();
            for (int s = 128; s > 0; s >>= 1) {
                if (tidl < s) red[tidl] += red[tidl + s];
                __syncthreads();
            }
            const float inv = 1.0f / red[0];
            __syncthreads();
            for (int j = tidl; j < LL; j += 256) row[j] *= inv;
            __syncthreads();
        }
    }
    grid_bar();

    {   // out_attn = V @ attn^T
        const size_t total = (size_t)BB * CC * LL;
        for (size_t w = gtid; w < total; w += nthr) {
            int i = (int)(w % LL);
            int cc = (int)((w / LL) % CC);
            int b = (int)(w / ((size_t)CC * LL));
            const float* vrow = g_V + ((size_t)b * CC + cc) * LL;
            const float* prow = g_E + ((size_t)b * LL + i) * LL;
            float s = 0.0f;
            for (int j = 0; j < LL; j++) s = fmaf(vrow[j], prow[j], s);
            g_O[((size_t)b * CC + cc) * LL + i] = s;
        }
    }
    grid_bar();

    {   // bottom half = gamma * (Wc @ O + bc)
        const size_t total = (size_t)BB * CC * LL;
        for (size_t w = gtid; w < total; w += nthr) {
            int l = (int)(w % LL);
            int o = (int)((w / LL) % CC);
            int b = (int)(w / ((size_t)CC * LL));
            float s = bc[o];
            for (int cc = 0; cc < CC; cc++)
                s = fmaf(Wc[o * CC + cc], g_O[((size_t)b * CC + cc) * LL + l], s);
            out[(size_t)b * (2 * CC) * LL + (size_t)(CC + o) * LL + l] = gma * s;
        }
    }
}

// ---------------------------------------------------------------------------
// Fused kernel. 4-stage pipeline, sync per 2 chunks. gamma==0 zero-fill is
// hoisted BEFORE the mainloop so its L2/DRAM writes drain under compute.
// ---------------------------------------------------------------------------
extern "C" __global__ void __launch_bounds__(256, 2)
fused_attn_conv(const float* __restrict__ x,
                const float* __restrict__ Wv,
                const float* __restrict__ bv,
                const float* __restrict__ Wq, const float* __restrict__ bq,
                const float* __restrict__ Wk, const float* __restrict__ bk,
                const float* __restrict__ Wc, const float* __restrict__ bc,
                const float* __restrict__ gamma,
                float* __restrict__ out)
{
    extern __shared__ char sm[];
    const uint32_t sb = smem_u32(sm);
    const int tid  = threadIdx.x;
    const int wid  = tid >> 5;
    const int lane = tid & 31;
    const int g    = lane >> 2;
    const int t    = lane & 3;
    const int wm   = wid >> 1;
    const int wn   = wid & 1;

    const int bn = blockIdx.x;         // 0..15
    const int bm = blockIdx.y;         // 0..1
    const int bb = blockIdx.z;         // 0..7

    const float gma = gamma[0];
    float* obase = out + (size_t)bb * (2 * CC) * LL;

    float c[2][8][4];
#pragma unroll
    for (int mt = 0; mt < 2; mt++)
#pragma unroll
        for (int nt = 0; nt < 8; nt++)
#pragma unroll
            for (int q = 0; q < 4; q++) c[mt][nt][q] = 0.0f;

    const float* Ag = Wv + (size_t)(bm * 128) * CIN;
    const float* Bg = x + (size_t)bb * CIN * LL + bn * 128;

    const int aRow = tid >> 2;
    const int aP   = tid & 3;
    const int bK   = tid >> 5;
    const int bP   = tid & 31;
    const uint32_t aOff = (uint32_t)(aRow * AROW + aP * 8);
    const uint32_t bOff = (uint32_t)(6144 + bK * BROW + bP * 8);

    const int lane15  = lane & 15;
    const uint32_t aLaneOff = (uint32_t)((wm * 32 + lane15) * AROW + (lane >> 4) * 16);
    const int bKrow = ((lane >> 3) & 1) * 8 + (lane & 7);
    const uint32_t bLaneOff = (uint32_t)(6144 + bKrow * BROW + (wn * 64 + (lane >> 4) * 8) * 2);

    float4 pa[2], pb[2];

    // ---- prologue: chunks 0,1 into stages 0,1; chunk 2 into regs ----
#pragma unroll
    for (int pc = 0; pc < 2; pc++) {
        const int k0 = pc * 16;
#pragma unroll
        for (int it = 0; it < 2; it++) {
            pa[it] = *(const float4*)(Ag + (size_t)(aRow + it * 64) * CIN + k0 + aP * 4);
            pb[it] = *(const float4*)(Bg + (size_t)(k0 + bK + it * 8) * LL + bP * 4);
        }
        const uint32_t st = sb + (uint32_t)(pc * STAGE);
#pragma unroll
        for (int it = 0; it < 2; it++) {
            cvt_store4(st + aOff + (uint32_t)(it * 64 * AROW), pa[it]);
            cvt_store4(st + bOff + (uint32_t)(it * 8 * BROW), pb[it]);
        }
    }
#pragma unroll
    for (int it = 0; it < 2; it++) {
        pa[it] = *(const float4*)(Ag + (size_t)(aRow + it * 64) * CIN + 32 + aP * 4);
        pb[it] = *(const float4*)(Bg + (size_t)(32 + bK + it * 8) * LL + bP * 4);
    }

    // ---- hoisted zero-fill (gamma == 0): drains under the whole mainloop ----
    if (gma == 0.0f) {
        float* zbase = obase + (size_t)(CC + bm * 128) * LL + bn * 128;
        const float4 z = make_float4(0.f, 0.f, 0.f, 0.f);
#pragma unroll
        for (int i = 0; i < 16; i++) {
            int idx = i * 256 + tid;       // 4096 float4 = 64 KB
            int r   = idx >> 5;
            int cq  = idx & 31;
            *(float4*)(zbase + (size_t)r * LL + cq * 4) = z;
        }
    }
    __syncthreads();

    for (int ch = 0; ch < 32; ch++) {
        const uint32_t cur = sb + (uint32_t)((ch & 3) * STAGE);

        // STS chunk ch+2 (regs loaded last iteration) into stage (ch+2)%4.
        if (ch < 30) {
            const uint32_t nxt = sb + (uint32_t)(((ch + 2) & 3) * STAGE);
#pragma unroll
            for (int it = 0; it < 2; it++) {
                cvt_store4(nxt + aOff + (uint32_t)(it * 64 * AROW), pa[it]);
                cvt_store4(nxt + bOff + (uint32_t)(it * 8 * BROW), pb[it]);
            }
        }
        // LDG chunk ch+3 into regs.
        if (ch < 29) {
            const int k0 = (ch + 3) * 16;
#pragma unroll
            for (int it = 0; it < 2; it++) {
                pa[it] = *(const float4*)(Ag + (size_t)(aRow + it * 64) * CIN + k0 + aP * 4);
                pb[it] = *(const float4*)(Bg + (size_t)(k0 + bK + it * 8) * LL + bP * 4);
            }
        }

        // compute chunk ch
        {
            uint32_t Ah[2][4], Bf[4][4];
#pragma unroll
            for (int mt = 0; mt < 2; mt++)
                LDSM_X4(Ah[mt][0], Ah[mt][1], Ah[mt][2], Ah[mt][3],
                        cur + aLaneOff + (uint32_t)(mt * 16 * AROW));
#pragma unroll
            for (int n2 = 0; n2 < 4; n2++)
                LDSM_X4_T(Bf[n2][0], Bf[n2][1], Bf[n2][2], Bf[n2][3],
                          cur + bLaneOff + (uint32_t)(n2 * 32));
#pragma unroll
            for (int mt = 0; mt < 2; mt++)
#pragma unroll
                for (int n2 = 0; n2 < 4; n2++) {
                    mma16816(c[mt][2*n2][0], c[mt][2*n2][1], c[mt][2*n2][2], c[mt][2*n2][3],
                             Ah[mt][0], Ah[mt][1], Ah[mt][2], Ah[mt][3],
                             Bf[n2][0], Bf[n2][1]);
                    mma16816(c[mt][2*n2+1][0], c[mt][2*n2+1][1], c[mt][2*n2+1][2], c[mt][2*n2+1][3],
                             Ah[mt][0], Ah[mt][1], Ah[mt][2], Ah[mt][3],
                             Bf[n2][2], Bf[n2][3]);
                }
        }
        if (ch & 1) __syncthreads();   // one barrier per 2 chunks (4 stages)
    }

    // ---- epilogue: top half (+bias); g_V mirror only when gamma != 0 ----
#pragma unroll
    for (int mt = 0; mt < 2; mt++) {
        const int m0 = bm * 128 + wm * 32 + mt * 16 + g;
        const float bv0 = bv[m0];
        const float bv1 = bv[m0 + 8];
#pragma unroll
        for (int nt = 0; nt < 8; nt++) {
            const int l0 = bn * 128 + wn * 64 + nt * 8 + 2 * t;
            float2 r0 = make_float2(c[mt][nt][0] + bv0, c[mt][nt][1] + bv0);
            float2 r1 = make_float2(c[mt][nt][2] + bv1, c[mt][nt][3] + bv1);
            *(float2*)(obase + (size_t)(m0    ) * LL + l0) = r0;
            *(float2*)(obase + (size_t)(m0 + 8) * LL + l0) = r1;
            if (gma != 0.0f) {
                float* vs = g_V + (size_t)bb * CC * LL;
                *(float2*)(vs + (size_t)(m0    ) * LL + l0) = r0;
                *(float2*)(vs + (size_t)(m0 + 8) * LL + l0) = r1;
            }
        }
    }

    // ---- gamma != 0: attention fallback in this same launch ----
    if (gma != 0.0f) {
        grid_bar();   // g_V complete across the grid
        fallback_phases(Wq, bq, Wk, bk, Wc, bc, gma, out, (float*)sm);
    }
}

// ---------------------------------------------------------------------------
extern "C" void kernel_launch(void* const* d_in, const int* in_sizes, int n_in,
                              void* d_out, int out_size)
{
    const float* x     = (const float*)d_in[0];
    const float* Wv    = (const float*)d_in[1];
    const float* bv    = (const float*)d_in[2];
    const float* Wq    = (const float*)d_in[3];
    const float* bq    = (const float*)d_in[4];
    const float* Wk    = (const float*)d_in[5];
    const float* bk    = (const float*)d_in[6];
    const float* Wc    = (const float*)d_in[7];
    const float* bc    = (const float*)d_in[8];
    const float* gamma = (const float*)d_in[9];
    float* out = (float*)d_out;

    dim3 grid(16, 2, 8);   // 256 CTAs, all resident at occ 2
    fused_attn_conv<<<grid, 256, SM_TOT>>>(x, Wv, bv, Wq, bq, Wk, bk,
                                           Wc, bc, gamma, out);
}

// round 14
// speedup vs baseline: 1.9650x; 1.0713x over previous
#include <cuda_runtime.h>
#include <cuda_fp16.h>
#include <cstdint>
#include <math.h>

#define BB   8
#define CIN  512
#define CC   256
#define LL   2048

#define NCTAS 256   // all resident: occ 2 x 148 SMs = 296 slots

// ---------------------------------------------------------------------------
// Scratch for the gamma != 0 fallback path.
// ---------------------------------------------------------------------------
__device__ float g_V[BB * CC * LL];
__device__ float g_Q[BB * CC * LL];
__device__ float g_K[BB * CC * LL];
__device__ float g_O[BB * CC * LL];
__device__ float g_E[BB * LL * LL];
__device__ unsigned g_count = 0;
__device__ unsigned g_sense = 0;

// ---------------------------------------------------------------------------
// mma.sync m16n8k16 fp16 + ldmatrix (sm_75/80 baseline — not arch-gated)
// ---------------------------------------------------------------------------
__device__ __forceinline__ void mma16816(float& c0, float& c1, float& c2, float& c3,
                                         uint32_t a0, uint32_t a1, uint32_t a2, uint32_t a3,
                                         uint32_t b0, uint32_t b1)
{
    asm volatile(
        "mma.sync.aligned.m16n8k16.row.col.f32.f16.f16.f32 "
        "{%0,%1,%2,%3}, {%4,%5,%6,%7}, {%8,%9}, {%0,%1,%2,%3};"
        : "+f"(c0), "+f"(c1), "+f"(c2), "+f"(c3)
        : "r"(a0), "r"(a1), "r"(a2), "r"(a3), "r"(b0), "r"(b1));
}

#define LDSM_X4(R0,R1,R2,R3,ADDR) \
    asm volatile("ldmatrix.sync.aligned.m8n8.x4.shared.b16 {%0,%1,%2,%3}, [%4];" \
        : "=r"(R0), "=r"(R1), "=r"(R2), "=r"(R3) : "r"(ADDR))
#define LDSM_X4_T(R0,R1,R2,R3,ADDR) \
    asm volatile("ldmatrix.sync.aligned.m8n8.x4.trans.shared.b16 {%0,%1,%2,%3}, [%4];" \
        : "=r"(R0), "=r"(R1), "=r"(R2), "=r"(R3) : "r"(ADDR))

__device__ __forceinline__ uint32_t smem_u32(const void* p) {
    uint32_t a;
    asm("{ .reg .u64 t; cvta.to.shared.u64 t, %1; cvt.u32.u64 %0, t; }"
        : "=r"(a) : "l"(p));
    return a;
}

__device__ __forceinline__ uint32_t pack_f16x2(float a, float b) {
    __half2 h = __halves2half2(__float2half_rn(a), __float2half_rn(b));
    return *reinterpret_cast<uint32_t*>(&h);
}

__device__ __forceinline__ void cvt_store4(uint32_t addr, float4 v) {
    uint32_t h01 = pack_f16x2(v.x, v.y);
    uint32_t h23 = pack_f16x2(v.z, v.w);
    asm volatile("st.shared.v2.u32 [%0], {%1,%2};" :: "r"(addr), "r"(h01), "r"(h23) : "memory");
}

// Self-resetting sense-reversing grid barrier (all NCTAS resident).
__device__ void grid_bar() {
    __syncthreads();
    if (threadIdx.x == 0) {
        unsigned s = *(volatile unsigned*)&g_sense;
        __threadfence();
        if (atomicAdd(&g_count, 1u) == NCTAS - 1u) {
            g_count = 0;
            __threadfence();
            *(volatile unsigned*)&g_sense = s ^ 1u;
        } else {
            while (*(volatile unsigned*)&g_sense == s) __nanosleep(100);
        }
    }
    __syncthreads();
    __threadfence();
}

// Smem: 4-stage pipeline, BK=16 per stage.
// A: [128 m][16 k] fp16, row 32 B pad 48 -> 6144 B.  ldmatrix phase m*3 mod 8 distinct.
// B: [16 k][128 n] fp16, row 256 B pad 272 -> 4352 B. ldmatrix.trans phase k*17 mod 8 distinct.
#define AROW   48
#define BROW   272
#define STAGE  10496
#define SM_TOT 41984
//
// Sync-every-2 safety (4 stages, barriers after odd iters):
//  - compute(ch) reads stage ch%4: A written at even iter ch-2/ch-3, B at ch-2;
//    the barrier after ch-1 (ch even) or ch-2 (ch odd) orders write->read.
//  - B STS at iter ch targets (ch+2)%4 = (ch-2)%4, last read at iter ch-2,
//    behind the barrier after ch-1 / ch-2.
//  - A STS at even iter ch targets (ch+2)%4 AND (ch+3)%4 = (ch-1)%4; stage
//    (ch-1)%4 was last read at iter ch-1, behind the barrier that ended it.

// ---------------------------------------------------------------------------
// Fallback attention phases (gamma != 0 only).
// ---------------------------------------------------------------------------
__device__ __noinline__ void fallback_phases(
    const float* __restrict__ Wq, const float* __restrict__ bq,
    const float* __restrict__ Wk, const float* __restrict__ bk,
    const float* __restrict__ Wc, const float* __restrict__ bc,
    float gma, float* __restrict__ out, float* red /*smem, 256 floats*/)
{
    const int nthr = NCTAS * 256;
    const int cta  = blockIdx.x + blockIdx.y * 16 + blockIdx.z * 32;
    const int gtid = cta * 256 + threadIdx.x;

    {   // Q, K projections
        const size_t total = (size_t)BB * CC * LL;
        for (size_t w = gtid; w < total; w += nthr) {
            int l = (int)(w % LL);
            int o = (int)((w / LL) % CC);
            int b = (int)(w / ((size_t)CC * LL));
            float sq = bq[o], sk = bk[o];
            for (int cc = 0; cc < CC; cc++) {
                float vv = g_V[((size_t)b * CC + cc) * LL + l];
                sq = fmaf(Wq[o * CC + cc], vv, sq);
                sk = fmaf(Wk[o * CC + cc], vv, sk);
            }
            g_Q[w] = sq; g_K[w] = sk;
        }
    }
    grid_bar();

    {   // energy
        const size_t total = (size_t)BB * LL * LL;
        for (size_t w = gtid; w < total; w += nthr) {
            int j = (int)(w % LL);
            int i = (int)((w / LL) % LL);
            int b = (int)(w / ((size_t)LL * LL));
            float s = 0.0f;
            for (int cc = 0; cc < CC; cc++)
                s = fmaf(g_Q[((size_t)b * CC + cc) * LL + i],
                         g_K[((size_t)b * CC + cc) * LL + j], s);
            g_E[w] = s;
        }
    }
    grid_bar();

    {   // softmax rows
        const int tidl = threadIdx.x;
        for (int r = cta; r < BB * LL; r += NCTAS) {
            float* row = g_E + (size_t)r * LL;
            float mx = -INFINITY;
            for (int j = tidl; j < LL; j += 256) mx = fmaxf(mx, row[j]);
            red[tidl] = mx; __syncthreads();
            for (int s = 128; s > 0; s >>= 1) {
                if (tidl < s) red[tidl] = fmaxf(red[tidl], red[tidl + s]);
                __syncthreads();
            }
            mx = red[0]; __syncthreads();
            float sum = 0.0f;
            for (int j = tidl; j < LL; j += 256) {
                float e = expf(row[j] - mx);
                row[j] = e; sum += e;
            }
            red[tidl] = sum; __syncthreads();
            for (int s = 128; s > 0; s >>= 1) {
                if (tidl < s) red[tidl] += red[tidl + s];
                __syncthreads();
            }
            const float inv = 1.0f / red[0];
            __syncthreads();
            for (int j = tidl; j < LL; j += 256) row[j] *= inv;
            __syncthreads();
        }
    }
    grid_bar();

    {   // out_attn = V @ attn^T
        const size_t total = (size_t)BB * CC * LL;
        for (size_t w = gtid; w < total; w += nthr) {
            int i = (int)(w % LL);
            int cc = (int)((w / LL) % CC);
            int b = (int)(w / ((size_t)CC * LL));
            const float* vrow = g_V + ((size_t)b * CC + cc) * LL;
            const float* prow = g_E + ((size_t)b * LL + i) * LL;
            float s = 0.0f;
            for (int j = 0; j < LL; j++) s = fmaf(vrow[j], prow[j], s);
            g_O[((size_t)b * CC + cc) * LL + i] = s;
        }
    }
    grid_bar();

    {   // bottom half = gamma * (Wc @ O + bc)
        const size_t total = (size_t)BB * CC * LL;
        for (size_t w = gtid; w < total; w += nthr) {
            int l = (int)(w % LL);
            int o = (int)((w / LL) % CC);
            int b = (int)(w / ((size_t)CC * LL));
            float s = bc[o];
            for (int cc = 0; cc < CC; cc++)
                s = fmaf(Wc[o * CC + cc], g_O[((size_t)b * CC + cc) * LL + l], s);
            out[(size_t)b * (2 * CC) * LL + (size_t)(CC + o) * LL + l] = gma * s;
        }
    }
}

// ---------------------------------------------------------------------------
// Fused kernel. 4-stage pipeline, sync per 2 chunks, pair-width A loads
// (32-k windows -> full-line LDG: A wavefronts halved).
// ---------------------------------------------------------------------------
extern "C" __global__ void __launch_bounds__(256, 2)
fused_attn_conv(const float* __restrict__ x,
                const float* __restrict__ Wv,
                const float* __restrict__ bv,
                const float* __restrict__ Wq, const float* __restrict__ bq,
                const float* __restrict__ Wk, const float* __restrict__ bk,
                const float* __restrict__ Wc, const float* __restrict__ bc,
                const float* __restrict__ gamma,
                float* __restrict__ out)
{
    extern __shared__ char sm[];
    const uint32_t sb = smem_u32(sm);
    const int tid  = threadIdx.x;
    const int wid  = tid >> 5;
    const int lane = tid & 31;
    const int g    = lane >> 2;
    const int t    = lane & 3;
    const int wm   = wid >> 1;
    const int wn   = wid & 1;

    const int bn = blockIdx.x;         // 0..15
    const int bm = blockIdx.y;         // 0..1
    const int bb = blockIdx.z;         // 0..7

    const float gma = gamma[0];
    float* obase = out + (size_t)bb * (2 * CC) * LL;

    float c[2][8][4];
#pragma unroll
    for (int mt = 0; mt < 2; mt++)
#pragma unroll
        for (int nt = 0; nt < 8; nt++)
#pragma unroll
            for (int q = 0; q < 4; q++) c[mt][nt][q] = 0.0f;

    const float* Ag = Wv + (size_t)(bm * 128) * CIN;
    const float* Bg = x + (size_t)bb * CIN * LL + bn * 128;

    // A pair-loader coords: per instr a warp covers 4 rows x 128 B (full lines).
    const int aRow2 = tid >> 3;              // 0..31 (+32*it, it=0..3)
    const int aC    = tid & 7;               // float4 col in 32-k window
    const int aCip  = aC >> 2;               // chunk-in-pair (0/1) — per-thread const
    const uint32_t aSmOff = (uint32_t)((aC & 3) * 8);   // k-group offset in stage

    // B loader (unchanged; already full-line)
    const int bK = tid >> 5;
    const int bP = tid & 31;
    const uint32_t bOff = (uint32_t)(6144 + bK * BROW + bP * 8);

    // ldmatrix per-lane bases
    const int lane15  = lane & 15;
    const uint32_t aLaneOff = (uint32_t)((wm * 32 + lane15) * AROW + (lane >> 4) * 16);
    const int bKrow = ((lane >> 3) & 1) * 8 + (lane & 7);
    const uint32_t bLaneOff = (uint32_t)(6144 + bKrow * BROW + (wn * 64 + (lane >> 4) * 8) * 2);

    float4 paR[4];   // A pair prefetch: rows aRow2+32*it, 32-k window
    float4 pbR[2];   // B chunk prefetch

    // ---- prologue ----
    // A pair 0 (chunks 0,1) -> stages 0,1
#pragma unroll
    for (int it = 0; it < 4; it++)
        paR[it] = *(const float4*)(Ag + (size_t)(aRow2 + it * 32) * CIN + aC * 4);
    {
        const uint32_t stA = sb + (uint32_t)(aCip * STAGE);   // stage 0 or 1
#pragma unroll
        for (int it = 0; it < 4; it++)
            cvt_store4(stA + (uint32_t)((aRow2 + it * 32) * AROW) + aSmOff, paR[it]);
    }
    // B chunks 0,1 -> stages 0,1
#pragma unroll
    for (int pc = 0; pc < 2; pc++) {
#pragma unroll
        for (int it = 0; it < 2; it++)
            pbR[it] = *(const float4*)(Bg + (size_t)(pc * 16 + bK + it * 8) * LL + bP * 4);
        const uint32_t st = sb + (uint32_t)(pc * STAGE);
#pragma unroll
        for (int it = 0; it < 2; it++)
            cvt_store4(st + bOff + (uint32_t)(it * 8 * BROW), pbR[it]);
    }
    // prefetch: A pair 1 (chunks 2,3), B chunk 2
#pragma unroll
    for (int it = 0; it < 4; it++)
        paR[it] = *(const float4*)(Ag + (size_t)(aRow2 + it * 32) * CIN + 32 + aC * 4);
#pragma unroll
    for (int it = 0; it < 2; it++)
        pbR[it] = *(const float4*)(Bg + (size_t)(32 + bK + it * 8) * LL + bP * 4);

    // ---- hoisted zero-fill (gamma == 0): drains under the mainloop ----
    if (gma == 0.0f) {
        float* zbase = obase + (size_t)(CC + bm * 128) * LL + bn * 128;
        const float4 z = make_float4(0.f, 0.f, 0.f, 0.f);
#pragma unroll
        for (int i = 0; i < 16; i++) {
            int idx = i * 256 + tid;
            int r   = idx >> 5;
            int cq  = idx & 31;
            *(float4*)(zbase + (size_t)r * LL + cq * 4) = z;
        }
    }
    __syncthreads();

    for (int ch = 0; ch < 32; ch++) {
        const uint32_t cur = sb + (uint32_t)((ch & 3) * STAGE);

        if (!(ch & 1)) {
            // even iter: STS A for chunks ch+2, ch+3 (this thread's chunk = ch+2+aCip)
            if (ch < 30) {
                const uint32_t stA = sb + (uint32_t)(((ch + 2 + aCip) & 3) * STAGE);
#pragma unroll
                for (int it = 0; it < 4; it++)
                    cvt_store4(stA + (uint32_t)((aRow2 + it * 32) * AROW) + aSmOff, paR[it]);
            }
            // LDG A pair for chunks ch+4, ch+5
            if (ch < 28) {
                const int k0p = (ch + 4) * 16;
#pragma unroll
                for (int it = 0; it < 4; it++)
                    paR[it] = *(const float4*)(Ag + (size_t)(aRow2 + it * 32) * CIN + k0p + aC * 4);
            }
        }
        // B: STS chunk ch+2, LDG chunk ch+3
        if (ch < 30) {
            const uint32_t nxt = sb + (uint32_t)(((ch + 2) & 3) * STAGE);
#pragma unroll
            for (int it = 0; it < 2; it++)
                cvt_store4(nxt + bOff + (uint32_t)(it * 8 * BROW), pbR[it]);
        }
        if (ch < 29) {
            const int k0 = (ch + 3) * 16;
#pragma unroll
            for (int it = 0; it < 2; it++)
                pbR[it] = *(const float4*)(Bg + (size_t)(k0 + bK + it * 8) * LL + bP * 4);
        }

        // compute chunk ch
        {
            uint32_t Ah[2][4], Bf[4][4];
#pragma unroll
            for (int mt = 0; mt < 2; mt++)
                LDSM_X4(Ah[mt][0], Ah[mt][1], Ah[mt][2], Ah[mt][3],
                        cur + aLaneOff + (uint32_t)(mt * 16 * AROW));
#pragma unroll
            for (int n2 = 0; n2 < 4; n2++)
                LDSM_X4_T(Bf[n2][0], Bf[n2][1], Bf[n2][2], Bf[n2][3],
                          cur + bLaneOff + (uint32_t)(n2 * 32));
#pragma unroll
            for (int mt = 0; mt < 2; mt++)
#pragma unroll
                for (int n2 = 0; n2 < 4; n2++) {
                    mma16816(c[mt][2*n2][0], c[mt][2*n2][1], c[mt][2*n2][2], c[mt][2*n2][3],
                             Ah[mt][0], Ah[mt][1], Ah[mt][2], Ah[mt][3],
                             Bf[n2][0], Bf[n2][1]);
                    mma16816(c[mt][2*n2+1][0], c[mt][2*n2+1][1], c[mt][2*n2+1][2], c[mt][2*n2+1][3],
                             Ah[mt][0], Ah[mt][1], Ah[mt][2], Ah[mt][3],
                             Bf[n2][2], Bf[n2][3]);
                }
        }
        if (ch & 1) __syncthreads();
    }

    // ---- epilogue ----
#pragma unroll
    for (int mt = 0; mt < 2; mt++) {
        const int m0 = bm * 128 + wm * 32 + mt * 16 + g;
        const float bv0 = bv[m0];
        const float bv1 = bv[m0 + 8];
#pragma unroll
        for (int nt = 0; nt < 8; nt++) {
            const int l0 = bn * 128 + wn * 64 + nt * 8 + 2 * t;
            float2 r0 = make_float2(c[mt][nt][0] + bv0, c[mt][nt][1] + bv0);
            float2 r1 = make_float2(c[mt][nt][2] + bv1, c[mt][nt][3] + bv1);
            *(float2*)(obase + (size_t)(m0    ) * LL + l0) = r0;
            *(float2*)(obase + (size_t)(m0 + 8) * LL + l0) = r1;
            if (gma != 0.0f) {
                float* vs = g_V + (size_t)bb * CC * LL;
                *(float2*)(vs + (size_t)(m0    ) * LL + l0) = r0;
                *(float2*)(vs + (size_t)(m0 + 8) * LL + l0) = r1;
            }
        }
    }

    if (gma != 0.0f) {
        grid_bar();
        fallback_phases(Wq, bq, Wk, bk, Wc, bc, gma, out, (float*)sm);
    }
}

// ---------------------------------------------------------------------------
extern "C" void kernel_launch(void* const* d_in, const int* in_sizes, int n_in,
                              void* d_out, int out_size)
{
    const float* x     = (const float*)d_in[0];
    const float* Wv    = (const float*)d_in[1];
    const float* bv    = (const float*)d_in[2];
    const float* Wq    = (const float*)d_in[3];
    const float* bq    = (const float*)d_in[4];
    const float* Wk    = (const float*)d_in[5];
    const float* bk    = (const float*)d_in[6];
    const float* Wc    = (const float*)d_in[7];
    const float* bc    = (const float*)d_in[8];
    const float* gamma = (const float*)d_in[9];
    float* out = (float*)d_out;

    dim3 grid(16, 2, 8);   // 256 CTAs, all resident at occ 2
    fused_attn_conv<<<grid, 256, SM_TOT>>>(x, Wv, bv, Wq, bq, Wk, bk,
                                           Wc, bc, gamma, out);
}